// round 1
// baseline (speedup 1.0000x reference)
#include <cuda_runtime.h>

// ---------------- problem constants ----------------
#define S   2048
#define E   1024
#define H   16
#define D   64
#define Bn  2
#define M_ROWS (Bn * S)            // 4096
#define OUT_N  (Bn * S * E)        // 4,194,304
#define ATT_N  (134217728)         // Bn*H*S*S

// ---------------- device scratch (allocation-free) ----------------
__device__ float g_q[Bn * H * S * D];
__device__ float g_k[Bn * H * S * D];
__device__ float g_v[Bn * H * S * D];
__device__ float g_ctx[Bn * S * E];
__device__ float g_out[Bn * S * E];
__device__ float g_attn[ATT_N];

// ============================================================
// GEMM:  out = A[M,K] @ W[N,K]^T + bias[N]
// 128x128 tile, BK=8, 256 threads, 8x8 per thread, fp32.
// headsplit=1: write as [B,H,S,D]; headsplit=0: row-major [M,N].
// ============================================================
__global__ __launch_bounds__(256) void gemm_nt(
    const float* __restrict__ A, const float* __restrict__ W,
    const float* __restrict__ bias, float* __restrict__ out,
    int K, int N, int headsplit)
{
    __shared__ float As[8][128];
    __shared__ float Ws[8][128];
    const int tid = threadIdx.x;
    const int rowBase = blockIdx.y * 128;
    const int colBase = blockIdx.x * 128;
    const int lr = tid >> 1;           // 0..127
    const int lc = (tid & 1) * 4;      // 0 or 4
    const int ty = tid >> 4;           // 0..15
    const int tx = tid & 15;           // 0..15

    float acc[8][8];
#pragma unroll
    for (int i = 0; i < 8; i++)
#pragma unroll
        for (int j = 0; j < 8; j++) acc[i][j] = 0.f;

    const float* Arow = A + (size_t)(rowBase + lr) * K + lc;
    const float* Wrow = W + (size_t)(colBase + lr) * K + lc;

    for (int kk = 0; kk < K; kk += 8) {
        float4 avv = *(const float4*)(Arow + kk);
        float4 wvv = *(const float4*)(Wrow + kk);
        As[lc + 0][lr] = avv.x; As[lc + 1][lr] = avv.y;
        As[lc + 2][lr] = avv.z; As[lc + 3][lr] = avv.w;
        Ws[lc + 0][lr] = wvv.x; Ws[lc + 1][lr] = wvv.y;
        Ws[lc + 2][lr] = wvv.z; Ws[lc + 3][lr] = wvv.w;
        __syncthreads();
#pragma unroll
        for (int k = 0; k < 8; k++) {
            float4 a0 = *(const float4*)&As[k][ty * 8];
            float4 a1 = *(const float4*)&As[k][ty * 8 + 4];
            float4 b0 = *(const float4*)&Ws[k][tx * 8];
            float4 b1 = *(const float4*)&Ws[k][tx * 8 + 4];
            float a[8] = {a0.x, a0.y, a0.z, a0.w, a1.x, a1.y, a1.z, a1.w};
            float b[8] = {b0.x, b0.y, b0.z, b0.w, b1.x, b1.y, b1.z, b1.w};
#pragma unroll
            for (int i = 0; i < 8; i++)
#pragma unroll
                for (int j = 0; j < 8; j++)
                    acc[i][j] = fmaf(a[i], b[j], acc[i][j]);
        }
        __syncthreads();
    }

#pragma unroll
    for (int i = 0; i < 8; i++) {
        int m = rowBase + ty * 8 + i;
#pragma unroll
        for (int j = 0; j < 8; j++) {
            int n = colBase + tx * 8 + j;
            float v = acc[i][j] + bias[n];
            if (headsplit) {
                int b = m / S, s = m - b * S;
                int h = n / D, d = n - h * D;
                out[(((size_t)(b * H + h)) * S + s) * D + d] = v;
            } else {
                out[(size_t)m * N + n] = v;
            }
        }
    }
}

// ============================================================
// Scores: attn_raw[bh,i,j] = (q[bh,i,:] . k[bh,j,:]) / 8  for j<=i
// 64x64 tiles; fully-masked tiles skipped. q,k: [B,H,S,D]
// ============================================================
__global__ __launch_bounds__(256) void scores_kernel(
    const float* __restrict__ q, const float* __restrict__ k,
    float* __restrict__ attn)
{
    const int jt = blockIdx.x, it = blockIdx.y, bh = blockIdx.z;
    if (jt > it) return;
    __shared__ float Qs[64][68];   // [d][i]
    __shared__ float Ks[64][68];   // [d][j]
    const int tid = threadIdx.x;
    const int r0 = tid >> 4;            // 0..15
    const int c4 = (tid & 15) * 4;      // 0..60

    const float* qbase = q + ((size_t)bh * S + (size_t)it * 64) * D;
    const float* kbase = k + ((size_t)bh * S + (size_t)jt * 64) * D;
#pragma unroll
    for (int rr = 0; rr < 4; rr++) {
        int row = r0 + rr * 16;
        float4 qv = *(const float4*)(qbase + (size_t)row * D + c4);
        float4 kv = *(const float4*)(kbase + (size_t)row * D + c4);
        Qs[c4 + 0][row] = qv.x; Qs[c4 + 1][row] = qv.y;
        Qs[c4 + 2][row] = qv.z; Qs[c4 + 3][row] = qv.w;
        Ks[c4 + 0][row] = kv.x; Ks[c4 + 1][row] = kv.y;
        Ks[c4 + 2][row] = kv.z; Ks[c4 + 3][row] = kv.w;
    }
    __syncthreads();

    const int ti = tid >> 4, tj = tid & 15;
    float acc[4][4] = {};
#pragma unroll
    for (int kd = 0; kd < 64; kd++) {
        float4 a = *(const float4*)&Qs[kd][ti * 4];
        float4 b = *(const float4*)&Ks[kd][tj * 4];
        float av[4] = {a.x, a.y, a.z, a.w};
        float bv[4] = {b.x, b.y, b.z, b.w};
#pragma unroll
        for (int i = 0; i < 4; i++)
#pragma unroll
            for (int j = 0; j < 4; j++)
                acc[i][j] = fmaf(av[i], bv[j], acc[i][j]);
    }
#pragma unroll
    for (int i = 0; i < 4; i++) {
        int gi = it * 64 + ti * 4 + i;
        float* prow = attn + ((size_t)bh * S + gi) * S;
#pragma unroll
        for (int j = 0; j < 4; j++) {
            int gj = jt * 64 + tj * 4 + j;
            if (gj <= gi) prow[gj] = acc[i][j] * 0.125f;
        }
    }
}

// ============================================================
// Row softmax over valid prefix [0..i]; writes exact zeros beyond.
// One block (256 thr) per row; row lives in registers (8/thread).
// ============================================================
__global__ __launch_bounds__(256) void softmax_kernel(float* __restrict__ attn)
{
    const int row = blockIdx.x;         // bh*S + i
    const int i = row & (S - 1);
    float* p = attn + (size_t)row * S;
    const int valid = i + 1;
    const int tid = threadIdx.x;

    float v[8];
    float mx = -3.4e38f;
#pragma unroll
    for (int l = 0; l < 8; l++) {
        int j = tid + l * 256;
        v[l] = (j < valid) ? p[j] : -3.4e38f;
        mx = fmaxf(mx, v[l]);
    }
    __shared__ float red[256];
    red[tid] = mx; __syncthreads();
    for (int s = 128; s > 0; s >>= 1) {
        if (tid < s) red[tid] = fmaxf(red[tid], red[tid + s]);
        __syncthreads();
    }
    mx = red[0]; __syncthreads();

    float sum = 0.f;
#pragma unroll
    for (int l = 0; l < 8; l++) {
        int j = tid + l * 256;
        v[l] = (j < valid) ? __expf(v[l] - mx) : 0.f;
        sum += v[l];
    }
    red[tid] = sum; __syncthreads();
    for (int s = 128; s > 0; s >>= 1) {
        if (tid < s) red[tid] += red[tid + s];
        __syncthreads();
    }
    const float inv = 1.f / red[0];
#pragma unroll
    for (int l = 0; l < 8; l++) {
        int j = tid + l * 256;
        p[j] = v[l] * inv;           // masked entries: 0*inv = 0
    }
}

// ============================================================
// ctx[b,s,h,:] = attn[bh,s,:] @ v[bh,:,:]   (causal K-chunks only)
// writes context directly in [B,S,H,D] == [B,S,E] layout.
// ============================================================
__global__ __launch_bounds__(256) void av_kernel(
    const float* __restrict__ attn, const float* __restrict__ v,
    float* __restrict__ ctx)
{
    const int it = blockIdx.x, bh = blockIdx.y;
    __shared__ float Ps[64][68];   // [k][i]
    __shared__ float Vs[64][68];   // [k][d]
    const int tid = threadIdx.x;
    const int r0 = tid >> 4;
    const int c4 = (tid & 15) * 4;
    const int ti = tid >> 4, tj = tid & 15;
    float acc[4][4] = {};

    for (int kt = 0; kt <= it; kt++) {
#pragma unroll
        for (int rr = 0; rr < 4; rr++) {
            int row = r0 + rr * 16;
            float4 pv = *(const float4*)(attn +
                ((size_t)bh * S + (size_t)it * 64 + row) * S + (size_t)kt * 64 + c4);
            Ps[c4 + 0][row] = pv.x; Ps[c4 + 1][row] = pv.y;
            Ps[c4 + 2][row] = pv.z; Ps[c4 + 3][row] = pv.w;
            float4 vv = *(const float4*)(v +
                ((size_t)bh * S + (size_t)kt * 64 + row) * D + c4);
            *(float4*)&Vs[row][c4] = vv;
        }
        __syncthreads();
#pragma unroll
        for (int kd = 0; kd < 64; kd++) {
            float4 a = *(const float4*)&Ps[kd][ti * 4];
            float4 b = *(const float4*)&Vs[kd][tj * 4];
            float av_[4] = {a.x, a.y, a.z, a.w};
            float bv_[4] = {b.x, b.y, b.z, b.w};
#pragma unroll
            for (int i2 = 0; i2 < 4; i2++)
#pragma unroll
                for (int j = 0; j < 4; j++)
                    acc[i2][j] = fmaf(av_[i2], bv_[j], acc[i2][j]);
        }
        __syncthreads();
    }

    const int b = bh / H, h = bh - b * H;
#pragma unroll
    for (int i2 = 0; i2 < 4; i2++) {
        int s_ = it * 64 + ti * 4 + i2;
#pragma unroll
        for (int j = 0; j < 4; j++) {
            int d_ = tj * 4 + j;
            ctx[(((size_t)b * S + s_) * H + h) * D + d_] = acc[i2][j];
        }
    }
}

// ============================================================
// launch
// ============================================================
extern "C" void kernel_launch(void* const* d_in, const int* in_sizes, int n_in,
                              void* d_out_v, int out_size)
{
    const float* query = (const float*)d_in[0];
    const float* key_  = (const float*)d_in[1];
    const float* value = (const float*)d_in[2];
    // d_in[3] = mask (causal, baked into kernels)
    const float* Wq = (const float*)d_in[4];
    const float* bq = (const float*)d_in[5];
    const float* Wk = (const float*)d_in[6];
    const float* bk = (const float*)d_in[7];
    const float* Wv = (const float*)d_in[8];
    const float* bv = (const float*)d_in[9];
    const float* Wo = (const float*)d_in[10];
    const float* bo = (const float*)d_in[11];
    float* d_out = (float*)d_out_v;

    float *qp, *kp, *vp, *cp, *op, *ap;
    cudaGetSymbolAddress((void**)&qp, g_q);
    cudaGetSymbolAddress((void**)&kp, g_k);
    cudaGetSymbolAddress((void**)&vp, g_v);
    cudaGetSymbolAddress((void**)&cp, g_ctx);
    cudaGetSymbolAddress((void**)&op, g_out);
    cudaGetSymbolAddress((void**)&ap, g_attn);

    // Route tuple outputs (out, attn) based on harness's out_size.
    float* out_ptr;
    float* attn_ptr;
    long long osz = (long long)out_size;
    if (osz >= (long long)OUT_N + (long long)ATT_N) {
        out_ptr = d_out;            // [out | attn] concatenated
        attn_ptr = d_out + OUT_N;
    } else if (osz == (long long)OUT_N) {
        out_ptr = d_out;            // out only
        attn_ptr = ap;
    } else {
        attn_ptr = d_out;           // attn only
        out_ptr = op;
    }

    dim3 gP(E / 128, M_ROWS / 128);
    gemm_nt<<<gP, 256>>>(query, Wq, bq, qp, E, E, 1);
    gemm_nt<<<gP, 256>>>(key_,  Wk, bk, kp, E, E, 1);
    gemm_nt<<<gP, 256>>>(value, Wv, bv, vp, E, E, 1);

    dim3 gS(S / 64, S / 64, Bn * H);
    scores_kernel<<<gS, 256>>>(qp, kp, attn_ptr);

    softmax_kernel<<<Bn * H * S, 256>>>(attn_ptr);

    dim3 gA(S / 64, Bn * H);
    av_kernel<<<gA, 256>>>(attn_ptr, vp, cp);

    gemm_nt<<<gP, 256>>>(cp, Wo, bo, out_ptr, E, E, 0);
}

// round 2
// speedup vs baseline: 2.2798x; 2.2798x over previous
#include <cuda_runtime.h>
#include <cstdint>

// ---------------- problem constants ----------------
#define S   2048
#define E   1024
#define H   16
#define D   64
#define Bn  2
#define M_ROWS (Bn * S)
#define OUT_N  (Bn * S * E)
#define ATT_N  (134217728)
#define STR 20            // smem row stride in floats (16B aligned, conflict-free)

// ---------------- device scratch ----------------
__device__ float g_q[Bn * H * S * D];
__device__ float g_k[Bn * H * S * D];
__device__ float g_vt[Bn * H * D * S];   // V stored transposed: [b,h,d,s]
__device__ float g_ctx[Bn * S * E];
__device__ float g_out[OUT_N];
__device__ float g_attn[ATT_N];

// ---------------- tf32 mma helpers ----------------
__device__ __forceinline__ uint32_t cvt_tf32(float x) {
    uint32_t u; asm("cvt.rna.tf32.f32 %0, %1;" : "=r"(u) : "f"(x)); return u;
}
__device__ __forceinline__ void sts4(uint32_t* p, float4 v) {
    uint4 u; u.x = cvt_tf32(v.x); u.y = cvt_tf32(v.y);
    u.z = cvt_tf32(v.z); u.w = cvt_tf32(v.w);
    *(uint4*)p = u;
}
__device__ __forceinline__ void ldsm4(uint32_t r[4], uint32_t addr) {
    asm volatile("ldmatrix.sync.aligned.m8n8.x4.shared.b16 {%0,%1,%2,%3}, [%4];"
        : "=r"(r[0]), "=r"(r[1]), "=r"(r[2]), "=r"(r[3]) : "r"(addr));
}
__device__ __forceinline__ void mma8(float c[4], const uint32_t a[4],
                                     uint32_t b0, uint32_t b1) {
    asm volatile("mma.sync.aligned.m16n8k8.row.col.f32.tf32.tf32.f32 "
        "{%0,%1,%2,%3},{%4,%5,%6,%7},{%8,%9},{%0,%1,%2,%3};"
        : "+f"(c[0]), "+f"(c[1]), "+f"(c[2]), "+f"(c[3])
        : "r"(a[0]), "r"(a[1]), "r"(a[2]), "r"(a[3]), "r"(b0), "r"(b1));
}

// ============================================================
// GEMM: out = A[M,K] @ W[N,K]^T + bias   (N = E = 1024)
// 128x128 tile, BK=16, 256 threads, warps 2(m)x4(n), warp 64x32.
// MODE 0: row-major [M,E]; MODE 1: [b,h,s,d]; MODE 2: [b,h,d,s] (V^T)
// ============================================================
template<int MODE>
__global__ __launch_bounds__(256) void gemm_tf32(
    const float* __restrict__ A, const float* __restrict__ W,
    const float* __restrict__ bias, float* __restrict__ out, int K)
{
    __shared__ uint32_t As[128 * STR];
    __shared__ uint32_t Ws[128 * STR];
    const int tid = threadIdx.x, lane = tid & 31, warp = tid >> 5;
    const int rowBase = blockIdx.y * 128, colBase = blockIdx.x * 128;
    const int lr = tid >> 1, lk = (tid & 1) * 8;

    const float* Ap = A + (size_t)(rowBase + lr) * K + lk;
    const float* Wp = W + (size_t)(colBase + lr) * K + lk;
    float4 ra0 = *(const float4*)Ap,       ra1 = *(const float4*)(Ap + 4);
    float4 rw0 = *(const float4*)Wp,       rw1 = *(const float4*)(Wp + 4);

    float acc[4][4][4];
#pragma unroll
    for (int i = 0; i < 4; i++)
#pragma unroll
        for (int j = 0; j < 4; j++)
#pragma unroll
            for (int l = 0; l < 4; l++) acc[i][j][l] = 0.f;

    const int wm = warp & 1, wn = warp >> 1;
    const int asub = lane >> 3, ar = lane & 7;
    const uint32_t sA = (uint32_t)__cvta_generic_to_shared(As);
    const uint32_t sW = (uint32_t)__cvta_generic_to_shared(Ws);
    const uint32_t aAddr = sA + (((wm * 64 + ar + (asub & 1) * 8) * STR + (asub >> 1) * 4) << 2);
    const uint32_t bAddr = sW + (((wn * 32 + ar) * STR + asub * 4) << 2);
    uint32_t* sAw = As + lr * STR + lk;
    uint32_t* sWw = Ws + lr * STR + lk;

    for (int kk = 0; kk < K; kk += 16) {
        sts4(sAw, ra0); sts4(sAw + 4, ra1);
        sts4(sWw, rw0); sts4(sWw + 4, rw1);
        __syncthreads();
        if (kk + 16 < K) {
            ra0 = *(const float4*)(Ap + kk + 16); ra1 = *(const float4*)(Ap + kk + 20);
            rw0 = *(const float4*)(Wp + kk + 16); rw1 = *(const float4*)(Wp + kk + 20);
        }
        uint32_t bF[4][4];
#pragma unroll
        for (int nt = 0; nt < 4; nt++) ldsm4(bF[nt], bAddr + nt * (8 * STR * 4));
#pragma unroll
        for (int ks = 0; ks < 2; ks++) {
            uint32_t aF[4][4];
#pragma unroll
            for (int mt = 0; mt < 4; mt++) ldsm4(aF[mt], aAddr + mt * (16 * STR * 4) + ks * 32);
#pragma unroll
            for (int mt = 0; mt < 4; mt++)
#pragma unroll
                for (int nt = 0; nt < 4; nt++)
                    mma8(acc[mt][nt], aF[mt], bF[nt][ks * 2], bF[nt][ks * 2 + 1]);
        }
        __syncthreads();
    }

    const int gid = lane >> 2, tig = lane & 3;
#pragma unroll
    for (int nt = 0; nt < 4; nt++) {
        const int col0 = colBase + wn * 32 + nt * 8 + tig * 2;
        const float bb0 = bias[col0], bb1 = bias[col0 + 1];
#pragma unroll
        for (int mt = 0; mt < 4; mt++) {
            const int row0 = rowBase + wm * 64 + mt * 16 + gid;
            const float v00 = acc[mt][nt][0] + bb0, v01 = acc[mt][nt][1] + bb1;
            const float v10 = acc[mt][nt][2] + bb0, v11 = acc[mt][nt][3] + bb1;
            if (MODE == 0) {
                *(float2*)&out[(size_t)row0 * E + col0]       = make_float2(v00, v01);
                *(float2*)&out[(size_t)(row0 + 8) * E + col0] = make_float2(v10, v11);
            } else if (MODE == 1) {
                const int b = row0 >> 11, s0 = row0 & (S - 1);
                const int h = col0 >> 6, d0 = col0 & 63;
                const size_t base = ((size_t)(b * H + h)) * S;
                *(float2*)&out[(base + s0) * D + d0]     = make_float2(v00, v01);
                *(float2*)&out[(base + s0 + 8) * D + d0] = make_float2(v10, v11);
            } else {
                const int b = row0 >> 11, s0 = row0 & (S - 1);
                const int h = col0 >> 6, d0 = col0 & 63;
                const size_t base = ((size_t)(b * H + h)) * D;
                out[(base + d0) * S + s0]         = v00;
                out[(base + d0 + 1) * S + s0]     = v01;
                out[(base + d0) * S + s0 + 8]     = v10;
                out[(base + d0 + 1) * S + s0 + 8] = v11;
            }
        }
    }
}

// ============================================================
// Scores: attn[bh,i,j] = (q[bh,i,:].k[bh,j,:])/8 for j<=i
// 128x128 tiles via tf32 mma, causal tiles skipped.
// ============================================================
__global__ __launch_bounds__(256) void scores_tf32(
    const float* __restrict__ q, const float* __restrict__ k,
    float* __restrict__ attn)
{
    const int jt = blockIdx.x, it = blockIdx.y, bh = blockIdx.z;
    if (jt > it) return;
    __shared__ uint32_t Qs[128 * STR];
    __shared__ uint32_t Ks[128 * STR];
    const int tid = threadIdx.x, lane = tid & 31, warp = tid >> 5;
    const int lr = tid >> 1, lk = (tid & 1) * 8;

    const float* Qp = q + ((size_t)bh * S + it * 128 + lr) * D + lk;
    const float* Kp = k + ((size_t)bh * S + jt * 128 + lr) * D + lk;
    float4 rq0 = *(const float4*)Qp, rq1 = *(const float4*)(Qp + 4);
    float4 rk0 = *(const float4*)Kp, rk1 = *(const float4*)(Kp + 4);

    float acc[4][4][4];
#pragma unroll
    for (int i = 0; i < 4; i++)
#pragma unroll
        for (int j = 0; j < 4; j++)
#pragma unroll
            for (int l = 0; l < 4; l++) acc[i][j][l] = 0.f;

    const int wm = warp & 1, wn = warp >> 1;
    const int asub = lane >> 3, ar = lane & 7;
    const uint32_t sQ = (uint32_t)__cvta_generic_to_shared(Qs);
    const uint32_t sK = (uint32_t)__cvta_generic_to_shared(Ks);
    const uint32_t aAddr = sQ + (((wm * 64 + ar + (asub & 1) * 8) * STR + (asub >> 1) * 4) << 2);
    const uint32_t bAddr = sK + (((wn * 32 + ar) * STR + asub * 4) << 2);
    uint32_t* sQw = Qs + lr * STR + lk;
    uint32_t* sKw = Ks + lr * STR + lk;

    for (int kk = 0; kk < D; kk += 16) {
        sts4(sQw, rq0); sts4(sQw + 4, rq1);
        sts4(sKw, rk0); sts4(sKw + 4, rk1);
        __syncthreads();
        if (kk + 16 < D) {
            rq0 = *(const float4*)(Qp + kk + 16); rq1 = *(const float4*)(Qp + kk + 20);
            rk0 = *(const float4*)(Kp + kk + 16); rk1 = *(const float4*)(Kp + kk + 20);
        }
        uint32_t bF[4][4];
#pragma unroll
        for (int nt = 0; nt < 4; nt++) ldsm4(bF[nt], bAddr + nt * (8 * STR * 4));
#pragma unroll
        for (int ks = 0; ks < 2; ks++) {
            uint32_t aF[4][4];
#pragma unroll
            for (int mt = 0; mt < 4; mt++) ldsm4(aF[mt], aAddr + mt * (16 * STR * 4) + ks * 32);
#pragma unroll
            for (int mt = 0; mt < 4; mt++)
#pragma unroll
                for (int nt = 0; nt < 4; nt++)
                    mma8(acc[mt][nt], aF[mt], bF[nt][ks * 2], bF[nt][ks * 2 + 1]);
        }
        __syncthreads();
    }

    const int gid = lane >> 2, tig = lane & 3;
#pragma unroll
    for (int mt = 0; mt < 4; mt++) {
        const int gi = it * 128 + wm * 64 + mt * 16 + gid;
        float* r0 = attn + ((size_t)bh * S + gi) * S;
        float* r1 = attn + ((size_t)bh * S + gi + 8) * S;
#pragma unroll
        for (int nt = 0; nt < 4; nt++) {
            const int gj = jt * 128 + wn * 32 + nt * 8 + tig * 2;
            const float v00 = acc[mt][nt][0] * 0.125f, v01 = acc[mt][nt][1] * 0.125f;
            const float v10 = acc[mt][nt][2] * 0.125f, v11 = acc[mt][nt][3] * 0.125f;
            if (jt < it) {
                *(float2*)&r0[gj] = make_float2(v00, v01);
                *(float2*)&r1[gj] = make_float2(v10, v11);
            } else {
                if (gj     <= gi)     r0[gj]     = v00;
                if (gj + 1 <= gi)     r0[gj + 1] = v01;
                if (gj     <= gi + 8) r1[gj]     = v10;
                if (gj + 1 <= gi + 8) r1[gj + 1] = v11;
            }
        }
    }
}

// ============================================================
// Row softmax over valid prefix [0..i]; exact zeros beyond.
// ============================================================
__global__ __launch_bounds__(256) void softmax_kernel(float* __restrict__ attn)
{
    const int row = blockIdx.x;
    const int i = row & (S - 1);
    float* p = attn + (size_t)row * S;
    const int valid = i + 1;
    const int tid = threadIdx.x;

    float v[8];
    float mx = -3.4e38f;
#pragma unroll
    for (int l = 0; l < 8; l++) {
        int j = tid + l * 256;
        v[l] = (j < valid) ? p[j] : -3.4e38f;
        mx = fmaxf(mx, v[l]);
    }
    __shared__ float red[256];
    red[tid] = mx; __syncthreads();
    for (int s = 128; s > 0; s >>= 1) {
        if (tid < s) red[tid] = fmaxf(red[tid], red[tid + s]);
        __syncthreads();
    }
    mx = red[0]; __syncthreads();

    float sum = 0.f;
#pragma unroll
    for (int l = 0; l < 8; l++) {
        int j = tid + l * 256;
        v[l] = (j < valid) ? __expf(v[l] - mx) : 0.f;
        sum += v[l];
    }
    red[tid] = sum; __syncthreads();
    for (int s = 128; s > 0; s >>= 1) {
        if (tid < s) red[tid] += red[tid + s];
        __syncthreads();
    }
    const float inv = 1.f / red[0];
#pragma unroll
    for (int l = 0; l < 8; l++) {
        int j = tid + l * 256;
        p[j] = v[l] * inv;
    }
}

// ============================================================
// AV: ctx[b,s,h,:] = attn[bh,s,:] @ V  using V^T [b,h,d,s]
// 128 rows x 64 d per block; causal j-chunks only; P zeros above diag.
// warps 4(m)x2(n), warp 32x32.
// ============================================================
__global__ __launch_bounds__(256) void av_tf32(
    const float* __restrict__ attn, const float* __restrict__ vt,
    float* __restrict__ ctx)
{
    const int it = blockIdx.x, bh = blockIdx.y;
    __shared__ uint32_t Ps[128 * STR];
    __shared__ uint32_t Vs[64 * STR];
    const int tid = threadIdx.x, lane = tid & 31, warp = tid >> 5;

    const int lr = tid >> 1, lk = (tid & 1) * 8;       // P loader
    const int vr = tid >> 2, vk = (tid & 3) * 4;       // V loader
    const float* Pp = attn + ((size_t)bh * S + it * 128 + lr) * S + lk;
    const float* Vp = vt + ((size_t)bh * D + vr) * S + vk;

    const int nChunks = (it + 1) * 8;                  // 16-wide j chunks
    float4 rp0 = *(const float4*)Pp, rp1 = *(const float4*)(Pp + 4);
    float4 rv0 = *(const float4*)Vp;

    float acc[2][4][4];
#pragma unroll
    for (int i = 0; i < 2; i++)
#pragma unroll
        for (int j = 0; j < 4; j++)
#pragma unroll
            for (int l = 0; l < 4; l++) acc[i][j][l] = 0.f;

    const int wm = warp & 3, wn = warp >> 2;
    const int asub = lane >> 3, ar = lane & 7;
    const uint32_t sP = (uint32_t)__cvta_generic_to_shared(Ps);
    const uint32_t sV = (uint32_t)__cvta_generic_to_shared(Vs);
    const uint32_t aAddr = sP + (((wm * 32 + ar + (asub & 1) * 8) * STR + (asub >> 1) * 4) << 2);
    const uint32_t bAddr = sV + (((wn * 32 + ar) * STR + asub * 4) << 2);
    uint32_t* sPw = Ps + lr * STR + lk;
    uint32_t* sVw = Vs + vr * STR + vk;

    for (int kt = 0; kt < nChunks; kt++) {
        sts4(sPw, rp0); sts4(sPw + 4, rp1);
        sts4(sVw, rv0);
        __syncthreads();
        if (kt + 1 < nChunks) {
            const int jb = (kt + 1) * 16;
            rp0 = *(const float4*)(Pp + jb); rp1 = *(const float4*)(Pp + jb + 4);
            rv0 = *(const float4*)(Vp + jb);
        }
        uint32_t bF[4][4];
#pragma unroll
        for (int nt = 0; nt < 4; nt++) ldsm4(bF[nt], bAddr + nt * (8 * STR * 4));
#pragma unroll
        for (int ks = 0; ks < 2; ks++) {
            uint32_t aF[2][4];
#pragma unroll
            for (int mt = 0; mt < 2; mt++) ldsm4(aF[mt], aAddr + mt * (16 * STR * 4) + ks * 32);
#pragma unroll
            for (int mt = 0; mt < 2; mt++)
#pragma unroll
                for (int nt = 0; nt < 4; nt++)
                    mma8(acc[mt][nt], aF[mt], bF[nt][ks * 2], bF[nt][ks * 2 + 1]);
        }
        __syncthreads();
    }

    const int gid = lane >> 2, tig = lane & 3;
    const int b = bh >> 4, h = bh & 15;
#pragma unroll
    for (int mt = 0; mt < 2; mt++) {
        const int s0 = it * 128 + wm * 32 + mt * 16 + gid;
#pragma unroll
        for (int nt = 0; nt < 4; nt++) {
            const int d0 = wn * 32 + nt * 8 + tig * 2;
            *(float2*)&ctx[(((size_t)(b * S + s0)) * H + h) * D + d0] =
                make_float2(acc[mt][nt][0], acc[mt][nt][1]);
            *(float2*)&ctx[(((size_t)(b * S + s0 + 8)) * H + h) * D + d0] =
                make_float2(acc[mt][nt][2], acc[mt][nt][3]);
        }
    }
}

// ============================================================
// launch
// ============================================================
extern "C" void kernel_launch(void* const* d_in, const int* in_sizes, int n_in,
                              void* d_out_v, int out_size)
{
    const float* query = (const float*)d_in[0];
    const float* key_  = (const float*)d_in[1];
    const float* value = (const float*)d_in[2];
    const float* Wq = (const float*)d_in[4];
    const float* bq = (const float*)d_in[5];
    const float* Wk = (const float*)d_in[6];
    const float* bk = (const float*)d_in[7];
    const float* Wv = (const float*)d_in[8];
    const float* bv = (const float*)d_in[9];
    const float* Wo = (const float*)d_in[10];
    const float* bo = (const float*)d_in[11];
    float* d_out = (float*)d_out_v;

    float *qp, *kp, *vtp, *cp, *op, *ap;
    cudaGetSymbolAddress((void**)&qp,  g_q);
    cudaGetSymbolAddress((void**)&kp,  g_k);
    cudaGetSymbolAddress((void**)&vtp, g_vt);
    cudaGetSymbolAddress((void**)&cp,  g_ctx);
    cudaGetSymbolAddress((void**)&op,  g_out);
    cudaGetSymbolAddress((void**)&ap,  g_attn);

    float* out_ptr;
    float* attn_ptr;
    long long osz = (long long)out_size;
    if (osz >= (long long)OUT_N + (long long)ATT_N) {
        out_ptr = d_out; attn_ptr = d_out + OUT_N;
    } else if (osz == (long long)OUT_N) {
        out_ptr = d_out; attn_ptr = ap;
    } else {
        attn_ptr = d_out; out_ptr = op;
    }

    dim3 gP(E / 128, M_ROWS / 128);
    gemm_tf32<1><<<gP, 256>>>(query, Wq, bq, qp,  E);
    gemm_tf32<1><<<gP, 256>>>(key_,  Wk, bk, kp,  E);
    gemm_tf32<2><<<gP, 256>>>(value, Wv, bv, vtp, E);

    dim3 gS(S / 128, S / 128, Bn * H);
    scores_tf32<<<gS, 256>>>(qp, kp, attn_ptr);

    softmax_kernel<<<Bn * H * S, 256>>>(attn_ptr);

    dim3 gA(S / 128, Bn * H);
    av_tf32<<<gA, 256>>>(attn_ptr, vtp, cp);

    gemm_tf32<0><<<gP, 256>>>(cp, Wo, bo, out_ptr, E);
}

// round 4
// speedup vs baseline: 2.6897x; 1.1798x over previous
#include <cuda_runtime.h>
#include <cstdint>

// ---------------- problem constants ----------------
#define S   2048
#define E   1024
#define H   16
#define D   64
#define Bn  2
#define M_ROWS (Bn * S)
#define OUT_N  (Bn * S * E)
#define ATT_N  (134217728)
#define GSTR 20      // gemm smem stride (words)
#define FSTR 68      // fused Q/K smem stride
#define VST  132     // fused V^T smem stride
#define PST  132     // fused P smem stride

// ---------------- device scratch ----------------
__device__ float g_q[Bn * H * S * D];
__device__ float g_k[Bn * H * S * D];
__device__ float g_vt[Bn * H * D * S];   // V transposed: [b,h,d,s]
__device__ float g_ctx[Bn * S * E];
__device__ float g_out[OUT_N];
__device__ float g_attn[ATT_N];

// ---------------- helpers ----------------
__device__ __forceinline__ uint32_t cvt_tf32(float x) {
    uint32_t u; asm("cvt.rna.tf32.f32 %0, %1;" : "=r"(u) : "f"(x)); return u;
}
__device__ __forceinline__ void sts4(uint32_t* p, float4 v) {
    uint4 u; u.x = cvt_tf32(v.x); u.y = cvt_tf32(v.y);
    u.z = cvt_tf32(v.z); u.w = cvt_tf32(v.w);
    *(uint4*)p = u;
}
__device__ __forceinline__ void ldsm4(uint32_t r[4], uint32_t addr) {
    asm volatile("ldmatrix.sync.aligned.m8n8.x4.shared.b16 {%0,%1,%2,%3}, [%4];"
        : "=r"(r[0]), "=r"(r[1]), "=r"(r[2]), "=r"(r[3]) : "r"(addr));
}
__device__ __forceinline__ void mma8(float c[4], const uint32_t a[4],
                                     uint32_t b0, uint32_t b1) {
    asm volatile("mma.sync.aligned.m16n8k8.row.col.f32.tf32.tf32.f32 "
        "{%0,%1,%2,%3},{%4,%5,%6,%7},{%8,%9},{%0,%1,%2,%3};"
        : "+f"(c[0]), "+f"(c[1]), "+f"(c[2]), "+f"(c[3])
        : "r"(a[0]), "r"(a[1]), "r"(a[2]), "r"(a[3]), "r"(b0), "r"(b1));
}
__device__ __forceinline__ void cpa16(uint32_t dst, const float* src) {
    asm volatile("cp.async.ca.shared.global [%0], [%1], 16;" :: "r"(dst), "l"(src));
}
__device__ __forceinline__ void cp_commit() {
    asm volatile("cp.async.commit_group;");
}
__device__ __forceinline__ void cp_wait(int n) {
    if (n <= 0)      asm volatile("cp.async.wait_group 0;");
    else if (n == 1) asm volatile("cp.async.wait_group 1;");
    else             asm volatile("cp.async.wait_group 2;");
}

// ============================================================
// GEMM: out = A[M,K] @ W[N,K]^T + bias  (tf32, double-buffered)
// MODE 0: row-major [M,E] (fp32)
// MODE 1: [b,h,s,d]  tf32-rounded
// MODE 2: [b,h,d,s]  tf32-rounded (V^T)
// ============================================================
template<int MODE>
__global__ __launch_bounds__(256) void gemm_tf32(
    const float* __restrict__ A, const float* __restrict__ W,
    const float* __restrict__ bias, float* __restrict__ out, int K)
{
    __shared__ uint32_t As[2][128 * GSTR];
    __shared__ uint32_t Ws[2][128 * GSTR];
    const int tid = threadIdx.x, lane = tid & 31, warp = tid >> 5;
    const int rowBase = blockIdx.y * 128, colBase = blockIdx.x * 128;
    const int lr = tid >> 1, lk = (tid & 1) * 8;

    const float* Ap = A + (size_t)(rowBase + lr) * K + lk;
    const float* Wp = W + (size_t)(colBase + lr) * K + lk;
    float4 ra0 = *(const float4*)Ap, ra1 = *(const float4*)(Ap + 4);
    float4 rw0 = *(const float4*)Wp, rw1 = *(const float4*)(Wp + 4);

    float acc[4][4][4];
#pragma unroll
    for (int i = 0; i < 4; i++)
#pragma unroll
        for (int j = 0; j < 4; j++)
#pragma unroll
            for (int l = 0; l < 4; l++) acc[i][j][l] = 0.f;

    const int wm = warp & 1, wn = warp >> 1;
    const int asub = lane >> 3, ar = lane & 7;
    const uint32_t sA = (uint32_t)__cvta_generic_to_shared(&As[0][0]);
    const uint32_t sW = (uint32_t)__cvta_generic_to_shared(&Ws[0][0]);
    const uint32_t aOff = (((wm * 64 + ar + (asub & 1) * 8) * GSTR + (asub >> 1) * 4) << 2);
    const uint32_t bOff = (((wn * 32 + ar) * GSTR + asub * 4) << 2);
    const uint32_t bufBytes = 128 * GSTR * 4;

    // prologue: fill buffer 0
    sts4(&As[0][lr * GSTR + lk], ra0); sts4(&As[0][lr * GSTR + lk + 4], ra1);
    sts4(&Ws[0][lr * GSTR + lk], rw0); sts4(&Ws[0][lr * GSTR + lk + 4], rw1);
    __syncthreads();

    for (int kk = 0; kk < K; kk += 16) {
        const int cur = (kk >> 4) & 1;
        const bool more = (kk + 16 < K);
        if (more) {
            ra0 = *(const float4*)(Ap + kk + 16); ra1 = *(const float4*)(Ap + kk + 20);
            rw0 = *(const float4*)(Wp + kk + 16); rw1 = *(const float4*)(Wp + kk + 20);
        }
        const uint32_t aAddr = sA + cur * bufBytes + aOff;
        const uint32_t bAddr = sW + cur * bufBytes + bOff;
        uint32_t bF[4][4];
#pragma unroll
        for (int nt = 0; nt < 4; nt++) ldsm4(bF[nt], bAddr + nt * (8 * GSTR * 4));
#pragma unroll
        for (int ks = 0; ks < 2; ks++) {
            uint32_t aF[4][4];
#pragma unroll
            for (int mt = 0; mt < 4; mt++) ldsm4(aF[mt], aAddr + mt * (16 * GSTR * 4) + ks * 32);
#pragma unroll
            for (int mt = 0; mt < 4; mt++)
#pragma unroll
                for (int nt = 0; nt < 4; nt++)
                    mma8(acc[mt][nt], aF[mt], bF[nt][ks * 2], bF[nt][ks * 2 + 1]);
        }
        if (more) {
            const int nxt = cur ^ 1;
            sts4(&As[nxt][lr * GSTR + lk], ra0); sts4(&As[nxt][lr * GSTR + lk + 4], ra1);
            sts4(&Ws[nxt][lr * GSTR + lk], rw0); sts4(&Ws[nxt][lr * GSTR + lk + 4], rw1);
        }
        __syncthreads();
    }

    const int gid = lane >> 2, tig = lane & 3;
#pragma unroll
    for (int nt = 0; nt < 4; nt++) {
        const int col0 = colBase + wn * 32 + nt * 8 + tig * 2;
        const float bb0 = bias[col0], bb1 = bias[col0 + 1];
#pragma unroll
        for (int mt = 0; mt < 4; mt++) {
            const int row0 = rowBase + wm * 64 + mt * 16 + gid;
            float v00 = acc[mt][nt][0] + bb0, v01 = acc[mt][nt][1] + bb1;
            float v10 = acc[mt][nt][2] + bb0, v11 = acc[mt][nt][3] + bb1;
            if (MODE != 0) {  // pre-round to tf32 for downstream cp.async+mma
                v00 = __uint_as_float(cvt_tf32(v00));
                v01 = __uint_as_float(cvt_tf32(v01));
                v10 = __uint_as_float(cvt_tf32(v10));
                v11 = __uint_as_float(cvt_tf32(v11));
            }
            if (MODE == 0) {
                *(float2*)&out[(size_t)row0 * E + col0]       = make_float2(v00, v01);
                *(float2*)&out[(size_t)(row0 + 8) * E + col0] = make_float2(v10, v11);
            } else if (MODE == 1) {
                const int b = row0 >> 11, s0 = row0 & (S - 1);
                const int h = col0 >> 6, d0 = col0 & 63;
                const size_t base = ((size_t)(b * H + h)) * S;
                *(float2*)&out[(base + s0) * D + d0]     = make_float2(v00, v01);
                *(float2*)&out[(base + s0 + 8) * D + d0] = make_float2(v10, v11);
            } else {
                const int b = row0 >> 11, s0 = row0 & (S - 1);
                const int h = col0 >> 6, d0 = col0 & 63;
                const size_t base = ((size_t)(b * H + h)) * D;
                out[(base + d0) * S + s0]         = v00;
                out[(base + d0 + 1) * S + s0]     = v01;
                out[(base + d0) * S + s0 + 8]     = v10;
                out[(base + d0 + 1) * S + s0 + 8] = v11;
            }
        }
    }
}

// ============================================================
// Fused attention middle: scores + softmax + p-write + P@V
// One block per (bh, 128-row stripe). Two passes over jt tiles.
// Warp layout: 8 warps = wm(4 rows of 32) x wn(2 cols of 64).
// ============================================================
__device__ __forceinline__ void scores_tile(uint32_t aQ, uint32_t kb,
                                            float as[2][8][4]) {
#pragma unroll
    for (int mt = 0; mt < 2; mt++)
#pragma unroll
        for (int nt = 0; nt < 8; nt++)
#pragma unroll
            for (int c = 0; c < 4; c++) as[mt][nt][c] = 0.f;
#pragma unroll
    for (int kp = 0; kp < 4; kp++) {
        uint32_t bF[8][4];
#pragma unroll
        for (int nt = 0; nt < 8; nt++) ldsm4(bF[nt], kb + nt * (8 * FSTR * 4) + kp * 64);
#pragma unroll
        for (int k2 = 0; k2 < 2; k2++) {
            uint32_t aF[2][4];
#pragma unroll
            for (int mt = 0; mt < 2; mt++)
                ldsm4(aF[mt], aQ + mt * (16 * FSTR * 4) + (kp * 2 + k2) * 32);
#pragma unroll
            for (int mt = 0; mt < 2; mt++)
#pragma unroll
                for (int nt = 0; nt < 8; nt++)
                    mma8(as[mt][nt], aF[mt], bF[nt][k2 * 2], bF[nt][k2 * 2 + 1]);
        }
    }
}

extern __shared__ char fsm[];

__global__ __launch_bounds__(256, 1) void fused_attn(
    const float* __restrict__ q, const float* __restrict__ k,
    const float* __restrict__ vt, float* __restrict__ attn,
    float* __restrict__ ctx)
{
    const int bh = blockIdx.x;
    const int it = 15 - blockIdx.y;          // big stripes scheduled first
    const int tid = threadIdx.x, lane = tid & 31, warp = tid >> 5;
    const int wm = warp & 3, wn = warp >> 2;
    const int gid = lane >> 2, tig = lane & 3;
    const int asub = lane >> 3, ar = lane & 7;

    float* Qs   = (float*)fsm;               // 128*FSTR
    float* Ks   = Qs + 128 * FSTR;           // 2 buffers of 128*FSTR
    float* Vs   = Ks + 2 * 128 * FSTR;       // 64*VST
    float* Ps   = Vs + 64 * VST;             // 128*PST
    float* Mred = Ps + 128 * PST;            // [128][2]
    float* Zred = Mred + 256;                // [128][2]
    float* Mfin = Zred + 256;                // [128]
    float* Zfin = Mfin + 128;                // [128]

    const uint32_t sQ = (uint32_t)__cvta_generic_to_shared(Qs);
    const uint32_t sK = (uint32_t)__cvta_generic_to_shared(Ks);
    const uint32_t sV = (uint32_t)__cvta_generic_to_shared(Vs);
    const uint32_t sP = (uint32_t)__cvta_generic_to_shared(Ps);
    const uint32_t kBufB = 128 * FSTR * 4;

    // loader indices
    const int l_r = tid >> 1, l_h = tid & 1;         // Q/K: 128x64
    const int v_r = tid >> 2, v_q = tid & 3;         // V: 64x128

    const float* qbase = q + ((size_t)bh * S + (size_t)it * 128) * D;
    const float* kbase0 = k + (size_t)bh * S * D;
    const float* vbase = vt + ((size_t)bh * D + v_r) * S + v_q * 4;

    // ldsm base addresses
    const uint32_t aQ = sQ + (((wm * 32 + ar + (asub & 1) * 8) * FSTR + (asub >> 1) * 4) << 2);
    const uint32_t bK0 = sK + (((wn * 64 + ar) * FSTR + asub * 4) << 2);
    const uint32_t aP = sP + (((wm * 32 + ar + (asub & 1) * 8) * PST + (asub >> 1) * 4) << 2);
    const uint32_t bV = sV + (((wn * 32 + ar) * VST + asub * 4) << 2);

    // ---- load Q stripe + K tile 0 ----
#pragma unroll
    for (int i = 0; i < 8; i++)
        cpa16(sQ + ((l_r * FSTR + l_h * 32 + i * 4) << 2),
              qbase + l_r * 64 + l_h * 32 + i * 4);
    cp_commit();
#pragma unroll
    for (int i = 0; i < 8; i++)
        cpa16(sK + ((l_r * FSTR + l_h * 32 + i * 4) << 2),
              kbase0 + (size_t)l_r * 64 + l_h * 32 + i * 4);
    cp_commit();

    float as[2][8][4];
    float Mrun[2][2], Zrun[2][2];
#pragma unroll
    for (int mt = 0; mt < 2; mt++)
#pragma unroll
        for (int h = 0; h < 2; h++) { Mrun[mt][h] = -3.0e38f; Zrun[mt][h] = 0.f; }
    const bool owner = (wn == 0 && tig == 0);

    // =================== PASS 1: statistics ===================
    for (int jt = 0; jt <= it; jt++) {
        const int cur = jt & 1;
        if (jt < it) {
            const float* kb = kbase0 + (size_t)(jt + 1) * 128 * D;
#pragma unroll
            for (int i = 0; i < 8; i++)
                cpa16(sK + (cur ^ 1) * kBufB + ((l_r * FSTR + l_h * 32 + i * 4) << 2),
                      kb + (size_t)l_r * 64 + l_h * 32 + i * 4);
            cp_commit();
            cp_wait(1);
        } else cp_wait(0);
        __syncthreads();

        scores_tile(aQ, bK0 + cur * kBufB, as);

        // scale + causal mask (diag tile)
#pragma unroll
        for (int mt = 0; mt < 2; mt++)
#pragma unroll
            for (int nt = 0; nt < 8; nt++)
#pragma unroll
                for (int c = 0; c < 4; c++) as[mt][nt][c] *= 0.125f;
        if (jt == it) {
#pragma unroll
            for (int mt = 0; mt < 2; mt++)
#pragma unroll
                for (int nt = 0; nt < 8; nt++)
#pragma unroll
                    for (int c = 0; c < 4; c++) {
                        const int lj = wn * 64 + nt * 8 + tig * 2 + (c & 1);
                        const int li = wm * 32 + mt * 16 + gid + (c >> 1) * 8;
                        if (lj > li) as[mt][nt][c] = -3.0e38f;
                    }
        }
        // per-row tile max
        float lm[2][2];
#pragma unroll
        for (int mt = 0; mt < 2; mt++)
#pragma unroll
            for (int h = 0; h < 2; h++) {
                float m = -3.0e38f;
#pragma unroll
                for (int nt = 0; nt < 8; nt++) {
                    m = fmaxf(m, as[mt][nt][h * 2]);
                    m = fmaxf(m, as[mt][nt][h * 2 + 1]);
                }
#pragma unroll
                for (int d = 1; d <= 2; d <<= 1)
                    m = fmaxf(m, __shfl_xor_sync(0xffffffffu, m, d));
                lm[mt][h] = m;
            }
        if (tig == 0) {
#pragma unroll
            for (int mt = 0; mt < 2; mt++)
#pragma unroll
                for (int h = 0; h < 2; h++)
                    Mred[(wm * 32 + mt * 16 + gid + h * 8) * 2 + wn] = lm[mt][h];
        }
        __syncthreads();
        float tmax[2][2], lz[2][2];
#pragma unroll
        for (int mt = 0; mt < 2; mt++)
#pragma unroll
            for (int h = 0; h < 2; h++) {
                const int r = wm * 32 + mt * 16 + gid + h * 8;
                tmax[mt][h] = fmaxf(Mred[r * 2], Mred[r * 2 + 1]);
                float z = 0.f;
#pragma unroll
                for (int nt = 0; nt < 8; nt++) {
                    z += __expf(as[mt][nt][h * 2]     - tmax[mt][h]);
                    z += __expf(as[mt][nt][h * 2 + 1] - tmax[mt][h]);
                }
#pragma unroll
                for (int d = 1; d <= 2; d <<= 1)
                    z += __shfl_xor_sync(0xffffffffu, z, d);
                lz[mt][h] = z;
            }
        if (tig == 0) {
#pragma unroll
            for (int mt = 0; mt < 2; mt++)
#pragma unroll
                for (int h = 0; h < 2; h++)
                    Zred[(wm * 32 + mt * 16 + gid + h * 8) * 2 + wn] = lz[mt][h];
        }
        __syncthreads();
        if (owner) {
#pragma unroll
            for (int mt = 0; mt < 2; mt++)
#pragma unroll
                for (int h = 0; h < 2; h++) {
                    const int r = wm * 32 + mt * 16 + gid + h * 8;
                    const float ts = Zred[r * 2] + Zred[r * 2 + 1];
                    const float tm = tmax[mt][h];
                    const float nm = fmaxf(Mrun[mt][h], tm);
                    Zrun[mt][h] = Zrun[mt][h] * __expf(Mrun[mt][h] - nm)
                                + ts * __expf(tm - nm);
                    Mrun[mt][h] = nm;
                }
        }
        __syncthreads();
    }

    // broadcast final stats
    if (owner) {
#pragma unroll
        for (int mt = 0; mt < 2; mt++)
#pragma unroll
            for (int h = 0; h < 2; h++) {
                const int r = wm * 32 + mt * 16 + gid + h * 8;
                Mfin[r] = Mrun[mt][h];
                Zfin[r] = 1.f / Zrun[mt][h];
            }
    }
    // restart K pipeline for pass 2
#pragma unroll
    for (int i = 0; i < 8; i++)
        cpa16(sK + ((l_r * FSTR + l_h * 32 + i * 4) << 2),
              kbase0 + (size_t)l_r * 64 + l_h * 32 + i * 4);
    cp_commit();
    __syncthreads();
    float Mr[2][2], Zi[2][2];
#pragma unroll
    for (int mt = 0; mt < 2; mt++)
#pragma unroll
        for (int h = 0; h < 2; h++) {
            const int r = wm * 32 + mt * 16 + gid + h * 8;
            Mr[mt][h] = Mfin[r]; Zi[mt][h] = Zfin[r];
        }

    // =================== PASS 2: p + P@V ===================
    float cacc[2][4][4];
#pragma unroll
    for (int mt = 0; mt < 2; mt++)
#pragma unroll
        for (int nt = 0; nt < 4; nt++)
#pragma unroll
            for (int c = 0; c < 4; c++) cacc[mt][nt][c] = 0.f;

    for (int jt = 0; jt <= it; jt++) {
        const int cur = jt & 1;
        // V tile
#pragma unroll
        for (int i = 0; i < 8; i++)
            cpa16(sV + ((v_r * VST + v_q * 4 + i * 16) << 2),
                  vbase + (size_t)jt * 128 + i * 16);
        cp_commit();
        if (jt < it) {
            const float* kb = kbase0 + (size_t)(jt + 1) * 128 * D;
#pragma unroll
            for (int i = 0; i < 8; i++)
                cpa16(sK + (cur ^ 1) * kBufB + ((l_r * FSTR + l_h * 32 + i * 4) << 2),
                      kb + (size_t)l_r * 64 + l_h * 32 + i * 4);
            cp_commit();
            cp_wait(2);
        } else cp_wait(1);
        __syncthreads();

        scores_tile(aQ, bK0 + cur * kBufB, as);

        // p = exp(s*scale - M)*invZ ; write to attn ; stage into Ps
        const bool diag = (jt == it);
#pragma unroll
        for (int mt = 0; mt < 2; mt++) {
#pragma unroll
            for (int h = 0; h < 2; h++) {
                const int rl = wm * 32 + mt * 16 + gid + h * 8;
                const int gi = it * 128 + rl;
                float* prow = attn + ((size_t)bh * S + gi) * S + jt * 128 + wn * 64;
                uint32_t* psrow = (uint32_t*)Ps + rl * PST + wn * 64;
#pragma unroll
                for (int nt = 0; nt < 8; nt++) {
                    float s0 = as[mt][nt][h * 2] * 0.125f;
                    float s1 = as[mt][nt][h * 2 + 1] * 0.125f;
                    float p0 = __expf(s0 - Mr[mt][h]) * Zi[mt][h];
                    float p1 = __expf(s1 - Mr[mt][h]) * Zi[mt][h];
                    if (diag) {
                        const int lj = wn * 64 + nt * 8 + tig * 2;
                        if (lj > rl)     p0 = 0.f;
                        if (lj + 1 > rl) p1 = 0.f;
                    }
                    *(float2*)(prow + nt * 8 + tig * 2) = make_float2(p0, p1);
                    uint2 pt; pt.x = cvt_tf32(p0); pt.y = cvt_tf32(p1);
                    *(uint2*)(psrow + nt * 8 + tig * 2) = pt;
                }
            }
        }
        cp_wait(jt < it ? 1 : 0);   // V arrived (next K may still fly)
        __syncthreads();

        // ctx += P @ V
#pragma unroll
        for (int kp = 0; kp < 8; kp++) {
            uint32_t bF[4][4];
#pragma unroll
            for (int nt = 0; nt < 4; nt++) ldsm4(bF[nt], bV + nt * (8 * VST * 4) + kp * 64);
#pragma unroll
            for (int k2 = 0; k2 < 2; k2++) {
                uint32_t aF[2][4];
#pragma unroll
                for (int mt = 0; mt < 2; mt++)
                    ldsm4(aF[mt], aP + mt * (16 * PST * 4) + (kp * 2 + k2) * 32);
#pragma unroll
                for (int mt = 0; mt < 2; mt++)
#pragma unroll
                    for (int nt = 0; nt < 4; nt++)
                        mma8(cacc[mt][nt], aF[mt], bF[nt][k2 * 2], bF[nt][k2 * 2 + 1]);
            }
        }
        __syncthreads();
    }

    // ctx epilogue: [b,s,h,d] == [B,S,E]
    const int b = bh >> 4, hh = bh & 15;
#pragma unroll
    for (int mt = 0; mt < 2; mt++) {
        const int s0 = it * 128 + wm * 32 + mt * 16 + gid;
#pragma unroll
        for (int nt = 0; nt < 4; nt++) {
            const int d0 = wn * 32 + nt * 8 + tig * 2;
            *(float2*)&ctx[((size_t)(b * S + s0)) * E + hh * D + d0] =
                make_float2(cacc[mt][nt][0], cacc[mt][nt][1]);
            *(float2*)&ctx[((size_t)(b * S + s0 + 8)) * E + hh * D + d0] =
                make_float2(cacc[mt][nt][2], cacc[mt][nt][3]);
        }
    }

    // zero-fill the unwritten columns (jt > it region)
    const int zc0 = (it + 1) * 128;
    if (zc0 < S) {
        const int r = tid >> 1;
        float* row = attn + ((size_t)bh * S + it * 128 + r) * S;
        const float4 z = make_float4(0.f, 0.f, 0.f, 0.f);
        for (int c = zc0 + (tid & 1) * 4; c < S; c += 8)
            *(float4*)(row + c) = z;
    }
}

// ============================================================
// launch
// ============================================================
extern "C" void kernel_launch(void* const* d_in, const int* in_sizes, int n_in,
                              void* d_out_v, int out_size)
{
    const float* query = (const float*)d_in[0];
    const float* key_  = (const float*)d_in[1];
    const float* value = (const float*)d_in[2];
    const float* Wq = (const float*)d_in[4];
    const float* bq = (const float*)d_in[5];
    const float* Wk = (const float*)d_in[6];
    const float* bk = (const float*)d_in[7];
    const float* Wv = (const float*)d_in[8];
    const float* bv = (const float*)d_in[9];
    const float* Wo = (const float*)d_in[10];
    const float* bo = (const float*)d_in[11];
    float* d_out = (float*)d_out_v;

    float *qp, *kp, *vtp, *cp, *op, *ap;
    cudaGetSymbolAddress((void**)&qp,  g_q);
    cudaGetSymbolAddress((void**)&kp,  g_k);
    cudaGetSymbolAddress((void**)&vtp, g_vt);
    cudaGetSymbolAddress((void**)&cp,  g_ctx);
    cudaGetSymbolAddress((void**)&op,  g_out);
    cudaGetSymbolAddress((void**)&ap,  g_attn);

    float* out_ptr;
    float* attn_ptr;
    long long osz = (long long)out_size;
    if (osz >= (long long)OUT_N + (long long)ATT_N) {
        out_ptr = d_out; attn_ptr = d_out + OUT_N;
    } else if (osz == (long long)OUT_N) {
        out_ptr = d_out; attn_ptr = ap;
    } else {
        attn_ptr = d_out; out_ptr = op;
    }

    const int FUSED_SMEM = (128 * FSTR + 2 * 128 * FSTR + 64 * VST + 128 * PST + 768) * 4;
    cudaFuncSetAttribute(fused_attn, cudaFuncAttributeMaxDynamicSharedMemorySize,
                         FUSED_SMEM);

    dim3 gP(E / 128, M_ROWS / 128);
    gemm_tf32<1><<<gP, 256>>>(query, Wq, bq, qp,  E);
    gemm_tf32<1><<<gP, 256>>>(key_,  Wk, bk, kp,  E);
    gemm_tf32<2><<<gP, 256>>>(value, Wv, bv, vtp, E);

    dim3 gF(Bn * H, 16);
    fused_attn<<<gF, 256, FUSED_SMEM>>>(qp, kp, vtp, attn_ptr, cp);

    gemm_tf32<0><<<gP, 256>>>(cp, Wo, bo, out_ptr, E);
}

// round 5
// speedup vs baseline: 3.1197x; 1.1599x over previous
#include <cuda_runtime.h>
#include <cstdint>

// ---------------- problem constants ----------------
#define S   2048
#define E   1024
#define H   16
#define D   64
#define Bn  2
#define M_ROWS (Bn * S)
#define OUT_N  (Bn * S * E)
#define ATT_N  (134217728)
#define GSTR 20      // gemm smem stride (words)
#define FSTR 68      // fused smem stride (words)

// ---------------- device scratch ----------------
__device__ float g_q[Bn * H * S * D];
__device__ float g_k[Bn * H * S * D];
__device__ float g_vt[Bn * H * D * S];   // V transposed: [b,h,d,s]
__device__ float g_ctx[Bn * S * E];
__device__ float g_out[OUT_N];
__device__ float g_attn[ATT_N];

// ---------------- helpers ----------------
__device__ __forceinline__ uint32_t cvt_tf32(float x) {
    uint32_t u; asm("cvt.rna.tf32.f32 %0, %1;" : "=r"(u) : "f"(x)); return u;
}
__device__ __forceinline__ void sts4(uint32_t* p, float4 v) {
    uint4 u; u.x = cvt_tf32(v.x); u.y = cvt_tf32(v.y);
    u.z = cvt_tf32(v.z); u.w = cvt_tf32(v.w);
    *(uint4*)p = u;
}
__device__ __forceinline__ void ldsm4(uint32_t r[4], uint32_t addr) {
    asm volatile("ldmatrix.sync.aligned.m8n8.x4.shared.b16 {%0,%1,%2,%3}, [%4];"
        : "=r"(r[0]), "=r"(r[1]), "=r"(r[2]), "=r"(r[3]) : "r"(addr));
}
__device__ __forceinline__ void mma8(float c[4], const uint32_t a[4],
                                     uint32_t b0, uint32_t b1) {
    asm volatile("mma.sync.aligned.m16n8k8.row.col.f32.tf32.tf32.f32 "
        "{%0,%1,%2,%3},{%4,%5,%6,%7},{%8,%9},{%0,%1,%2,%3};"
        : "+f"(c[0]), "+f"(c[1]), "+f"(c[2]), "+f"(c[3])
        : "r"(a[0]), "r"(a[1]), "r"(a[2]), "r"(a[3]), "r"(b0), "r"(b1));
}
__device__ __forceinline__ void cpa16(uint32_t dst, const float* src) {
    asm volatile("cp.async.ca.shared.global [%0], [%1], 16;" :: "r"(dst), "l"(src));
}
__device__ __forceinline__ void cp_commit() {
    asm volatile("cp.async.commit_group;");
}
__device__ __forceinline__ void cp_wait(int n) {
    if (n <= 0)      asm volatile("cp.async.wait_group 0;");
    else if (n == 1) asm volatile("cp.async.wait_group 1;");
    else             asm volatile("cp.async.wait_group 2;");
}

// ============================================================
// GEMM: out = A[M,K] @ W[N,K]^T + bias  (tf32, double-buffered)
// min_blocks=2 -> <=128 regs -> 2 blocks/SM.
// MODE 0: row-major [M,E]; 1: [b,h,s,d] tf32; 2: [b,h,d,s] tf32 (V^T)
// ============================================================
template<int MODE>
__global__ __launch_bounds__(256, 2) void gemm_tf32(
    const float* __restrict__ A, const float* __restrict__ W,
    const float* __restrict__ bias, float* __restrict__ out, int K)
{
    __shared__ uint32_t As[2][128 * GSTR];
    __shared__ uint32_t Ws[2][128 * GSTR];
    const int tid = threadIdx.x, lane = tid & 31, warp = tid >> 5;
    const int rowBase = blockIdx.y * 128, colBase = blockIdx.x * 128;
    const int lr = tid >> 1, lk = (tid & 1) * 8;

    const float* Ap = A + (size_t)(rowBase + lr) * K + lk;
    const float* Wp = W + (size_t)(colBase + lr) * K + lk;
    float4 ra0 = *(const float4*)Ap, ra1 = *(const float4*)(Ap + 4);
    float4 rw0 = *(const float4*)Wp, rw1 = *(const float4*)(Wp + 4);

    float acc[4][4][4];
#pragma unroll
    for (int i = 0; i < 4; i++)
#pragma unroll
        for (int j = 0; j < 4; j++)
#pragma unroll
            for (int l = 0; l < 4; l++) acc[i][j][l] = 0.f;

    const int wm = warp & 1, wn = warp >> 1;
    const int asub = lane >> 3, ar = lane & 7;
    const uint32_t sA = (uint32_t)__cvta_generic_to_shared(&As[0][0]);
    const uint32_t sW = (uint32_t)__cvta_generic_to_shared(&Ws[0][0]);
    const uint32_t aOff = (((wm * 64 + ar + (asub & 1) * 8) * GSTR + (asub >> 1) * 4) << 2);
    const uint32_t bOff = (((wn * 32 + ar) * GSTR + asub * 4) << 2);
    const uint32_t bufBytes = 128 * GSTR * 4;

    sts4(&As[0][lr * GSTR + lk], ra0); sts4(&As[0][lr * GSTR + lk + 4], ra1);
    sts4(&Ws[0][lr * GSTR + lk], rw0); sts4(&Ws[0][lr * GSTR + lk + 4], rw1);
    __syncthreads();

    for (int kk = 0; kk < K; kk += 16) {
        const int cur = (kk >> 4) & 1;
        const bool more = (kk + 16 < K);
        if (more) {
            ra0 = *(const float4*)(Ap + kk + 16); ra1 = *(const float4*)(Ap + kk + 20);
            rw0 = *(const float4*)(Wp + kk + 16); rw1 = *(const float4*)(Wp + kk + 20);
        }
        const uint32_t aAddr = sA + cur * bufBytes + aOff;
        const uint32_t bAddr = sW + cur * bufBytes + bOff;
        uint32_t bF[4][4];
#pragma unroll
        for (int nt = 0; nt < 4; nt++) ldsm4(bF[nt], bAddr + nt * (8 * GSTR * 4));
#pragma unroll
        for (int ks = 0; ks < 2; ks++) {
            uint32_t aF[4][4];
#pragma unroll
            for (int mt = 0; mt < 4; mt++) ldsm4(aF[mt], aAddr + mt * (16 * GSTR * 4) + ks * 32);
#pragma unroll
            for (int mt = 0; mt < 4; mt++)
#pragma unroll
                for (int nt = 0; nt < 4; nt++)
                    mma8(acc[mt][nt], aF[mt], bF[nt][ks * 2], bF[nt][ks * 2 + 1]);
        }
        if (more) {
            const int nxt = cur ^ 1;
            sts4(&As[nxt][lr * GSTR + lk], ra0); sts4(&As[nxt][lr * GSTR + lk + 4], ra1);
            sts4(&Ws[nxt][lr * GSTR + lk], rw0); sts4(&Ws[nxt][lr * GSTR + lk + 4], rw1);
        }
        __syncthreads();
    }

    const int gid = lane >> 2, tig = lane & 3;
#pragma unroll
    for (int nt = 0; nt < 4; nt++) {
        const int col0 = colBase + wn * 32 + nt * 8 + tig * 2;
        const float bb0 = bias[col0], bb1 = bias[col0 + 1];
#pragma unroll
        for (int mt = 0; mt < 4; mt++) {
            const int row0 = rowBase + wm * 64 + mt * 16 + gid;
            float v00 = acc[mt][nt][0] + bb0, v01 = acc[mt][nt][1] + bb1;
            float v10 = acc[mt][nt][2] + bb0, v11 = acc[mt][nt][3] + bb1;
            if (MODE != 0) {
                v00 = __uint_as_float(cvt_tf32(v00));
                v01 = __uint_as_float(cvt_tf32(v01));
                v10 = __uint_as_float(cvt_tf32(v10));
                v11 = __uint_as_float(cvt_tf32(v11));
            }
            if (MODE == 0) {
                *(float2*)&out[(size_t)row0 * E + col0]       = make_float2(v00, v01);
                *(float2*)&out[(size_t)(row0 + 8) * E + col0] = make_float2(v10, v11);
            } else if (MODE == 1) {
                const int b = row0 >> 11, s0 = row0 & (S - 1);
                const int h = col0 >> 6, d0 = col0 & 63;
                const size_t base = ((size_t)(b * H + h)) * S;
                *(float2*)&out[(base + s0) * D + d0]     = make_float2(v00, v01);
                *(float2*)&out[(base + s0 + 8) * D + d0] = make_float2(v10, v11);
            } else {
                const int b = row0 >> 11, s0 = row0 & (S - 1);
                const int h = col0 >> 6, d0 = col0 & 63;
                const size_t base = ((size_t)(b * H + h)) * D;
                out[(base + d0) * S + s0]         = v00;
                out[(base + d0 + 1) * S + s0]     = v01;
                out[(base + d0) * S + s0 + 8]     = v10;
                out[(base + d0 + 1) * S + s0 + 8] = v11;
            }
        }
    }
}

// ============================================================
// Fused attention: 64-row stripe x 64-col jt tiles, 2 blocks/SM.
// 8 warps = wm(4 x 16 rows) x wn(2 x 32 cols).
// ============================================================
extern __shared__ char fsm[];

__device__ __forceinline__ void scores_tile64(uint32_t aQ, uint32_t kb,
                                              float as[4][4]) {
#pragma unroll
    for (int nt = 0; nt < 4; nt++)
#pragma unroll
        for (int c = 0; c < 4; c++) as[nt][c] = 0.f;
#pragma unroll
    for (int kp = 0; kp < 4; kp++) {
        uint32_t bF[4][4];
#pragma unroll
        for (int nt = 0; nt < 4; nt++) ldsm4(bF[nt], kb + nt * (8 * FSTR * 4) + kp * 64);
#pragma unroll
        for (int k2 = 0; k2 < 2; k2++) {
            uint32_t aF[4];
            ldsm4(aF, aQ + (kp * 2 + k2) * 32);
#pragma unroll
            for (int nt = 0; nt < 4; nt++)
                mma8(as[nt], aF, bF[nt][k2 * 2], bF[nt][k2 * 2 + 1]);
        }
    }
}

__global__ __launch_bounds__(256, 2) void fused_attn(
    const float* __restrict__ q, const float* __restrict__ k,
    const float* __restrict__ vt, float* __restrict__ attn,
    float* __restrict__ ctx)
{
    const int bh = blockIdx.x;
    const int it = 31 - blockIdx.y;          // 32 stripes of 64, big-first
    const int tid = threadIdx.x, lane = tid & 31, warp = tid >> 5;
    const int wm = warp & 3, wn = warp >> 2;
    const int gid = lane >> 2, tig = lane & 3;
    const int asub = lane >> 3, ar = lane & 7;

    float* Qs   = (float*)fsm;               // 64*FSTR
    float* Ks   = Qs + 64 * FSTR;            // 2 x 64*FSTR
    float* Vs   = Ks + 2 * 64 * FSTR;        // 64*FSTR
    float* Ps   = Vs + 64 * FSTR;            // 64*FSTR
    float* Mred = Ps + 64 * FSTR;            // [64][2]
    float* Zred = Mred + 128;                // [64][2]
    float* Mfin = Zred + 128;                // [64]
    float* Zfin = Mfin + 64;                 // [64]

    const uint32_t sQ = (uint32_t)__cvta_generic_to_shared(Qs);
    const uint32_t sK = (uint32_t)__cvta_generic_to_shared(Ks);
    const uint32_t sV = (uint32_t)__cvta_generic_to_shared(Vs);
    const uint32_t sP = (uint32_t)__cvta_generic_to_shared(Ps);
    const uint32_t kBufB = 64 * FSTR * 4;

    const int l_r = tid >> 2, l_c = tid & 3;     // 64x64 loader: 4 f4/thread

    const float* qbase = q + ((size_t)bh * S + (size_t)it * 64) * D;
    const float* kbase0 = k + (size_t)bh * S * D;
    const float* vbase = vt + ((size_t)bh * D + l_r) * S + l_c * 4;

    const uint32_t aQ = sQ + (((wm * 16 + ar + (asub & 1) * 8) * FSTR + (asub >> 1) * 4) << 2);
    const uint32_t bK0 = sK + (((wn * 32 + ar) * FSTR + asub * 4) << 2);
    const uint32_t aP = sP + (((wm * 16 + ar + (asub & 1) * 8) * FSTR + (asub >> 1) * 4) << 2);
    const uint32_t bV = sV + (((wn * 32 + ar) * FSTR + asub * 4) << 2);

    // ---- load Q stripe + K tile 0 ----
#pragma unroll
    for (int i = 0; i < 4; i++)
        cpa16(sQ + ((l_r * FSTR + l_c * 4 + i * 16) << 2),
              qbase + l_r * 64 + l_c * 4 + i * 16);
    cp_commit();
#pragma unroll
    for (int i = 0; i < 4; i++)
        cpa16(sK + ((l_r * FSTR + l_c * 4 + i * 16) << 2),
              kbase0 + (size_t)l_r * 64 + l_c * 4 + i * 16);
    cp_commit();

    float as[4][4];
    float Mrun[2] = {-3.0e38f, -3.0e38f}, Zrun[2] = {0.f, 0.f};
    const bool owner = (wn == 0 && tig == 0);

    // =================== PASS 1: statistics ===================
    for (int jt = 0; jt <= it; jt++) {
        const int cur = jt & 1;
        if (jt < it) {
            const float* kb = kbase0 + (size_t)(jt + 1) * 64 * D;
#pragma unroll
            for (int i = 0; i < 4; i++)
                cpa16(sK + (cur ^ 1) * kBufB + ((l_r * FSTR + l_c * 4 + i * 16) << 2),
                      kb + (size_t)l_r * 64 + l_c * 4 + i * 16);
            cp_commit();
            cp_wait(1);
        } else cp_wait(0);
        __syncthreads();

        scores_tile64(aQ, bK0 + cur * kBufB, as);

#pragma unroll
        for (int nt = 0; nt < 4; nt++)
#pragma unroll
            for (int c = 0; c < 4; c++) as[nt][c] *= 0.125f;
        if (jt == it) {
#pragma unroll
            for (int nt = 0; nt < 4; nt++)
#pragma unroll
                for (int c = 0; c < 4; c++) {
                    const int lj = wn * 32 + nt * 8 + tig * 2 + (c & 1);
                    const int li = wm * 16 + gid + (c >> 1) * 8;
                    if (lj > li) as[nt][c] = -3.0e38f;
                }
        }
        float lm[2];
#pragma unroll
        for (int h = 0; h < 2; h++) {
            float m = -3.0e38f;
#pragma unroll
            for (int nt = 0; nt < 4; nt++) {
                m = fmaxf(m, as[nt][h * 2]);
                m = fmaxf(m, as[nt][h * 2 + 1]);
            }
#pragma unroll
            for (int d = 1; d <= 2; d <<= 1)
                m = fmaxf(m, __shfl_xor_sync(0xffffffffu, m, d));
            lm[h] = m;
        }
        if (tig == 0) {
#pragma unroll
            for (int h = 0; h < 2; h++)
                Mred[(wm * 16 + gid + h * 8) * 2 + wn] = lm[h];
        }
        __syncthreads();
        float tmax[2];
#pragma unroll
        for (int h = 0; h < 2; h++) {
            const int r = wm * 16 + gid + h * 8;
            tmax[h] = fmaxf(Mred[r * 2], Mred[r * 2 + 1]);
            float z = 0.f;
#pragma unroll
            for (int nt = 0; nt < 4; nt++) {
                z += __expf(as[nt][h * 2]     - tmax[h]);
                z += __expf(as[nt][h * 2 + 1] - tmax[h]);
            }
#pragma unroll
            for (int d = 1; d <= 2; d <<= 1)
                z += __shfl_xor_sync(0xffffffffu, z, d);
            if (tig == 0) Zred[r * 2 + wn] = z;
        }
        __syncthreads();
        if (owner) {
#pragma unroll
            for (int h = 0; h < 2; h++) {
                const int r = wm * 16 + gid + h * 8;
                const float ts = Zred[r * 2] + Zred[r * 2 + 1];
                const float tm = tmax[h];
                const float nm = fmaxf(Mrun[h], tm);
                Zrun[h] = Zrun[h] * __expf(Mrun[h] - nm) + ts * __expf(tm - nm);
                Mrun[h] = nm;
            }
        }
        __syncthreads();
    }

    if (owner) {
#pragma unroll
        for (int h = 0; h < 2; h++) {
            const int r = wm * 16 + gid + h * 8;
            Mfin[r] = Mrun[h];
            Zfin[r] = 1.f / Zrun[h];
        }
    }
    // restart K pipeline (buffer 0 = jt 0)
#pragma unroll
    for (int i = 0; i < 4; i++)
        cpa16(sK + ((l_r * FSTR + l_c * 4 + i * 16) << 2),
              kbase0 + (size_t)l_r * 64 + l_c * 4 + i * 16);
    cp_commit();
    __syncthreads();
    float Mr[2], Zi[2];
#pragma unroll
    for (int h = 0; h < 2; h++) {
        const int r = wm * 16 + gid + h * 8;
        Mr[h] = Mfin[r]; Zi[h] = Zfin[r];
    }

    // =================== PASS 2: p + P@V ===================
    float cacc[4][4];
#pragma unroll
    for (int nt = 0; nt < 4; nt++)
#pragma unroll
        for (int c = 0; c < 4; c++) cacc[nt][c] = 0.f;

    for (int jt = 0; jt <= it; jt++) {
        const int cur = jt & 1;
#pragma unroll
        for (int i = 0; i < 4; i++)
            cpa16(sV + ((l_r * FSTR + l_c * 4 + i * 16) << 2),
                  vbase + (size_t)jt * 64 + i * 16);
        cp_commit();
        if (jt < it) {
            const float* kb = kbase0 + (size_t)(jt + 1) * 64 * D;
#pragma unroll
            for (int i = 0; i < 4; i++)
                cpa16(sK + (cur ^ 1) * kBufB + ((l_r * FSTR + l_c * 4 + i * 16) << 2),
                      kb + (size_t)l_r * 64 + l_c * 4 + i * 16);
            cp_commit();
            cp_wait(2);
        } else cp_wait(1);
        __syncthreads();

        scores_tile64(aQ, bK0 + cur * kBufB, as);

        const bool diag = (jt == it);
#pragma unroll
        for (int h = 0; h < 2; h++) {
            const int rl = wm * 16 + gid + h * 8;
            const int gi = it * 64 + rl;
            float* prow = attn + ((size_t)bh * S + gi) * S + jt * 64 + wn * 32;
            uint32_t* psrow = (uint32_t*)Ps + rl * FSTR + wn * 32;
#pragma unroll
            for (int nt = 0; nt < 4; nt++) {
                float s0 = as[nt][h * 2] * 0.125f;
                float s1 = as[nt][h * 2 + 1] * 0.125f;
                float p0 = __expf(s0 - Mr[h]) * Zi[h];
                float p1 = __expf(s1 - Mr[h]) * Zi[h];
                if (diag) {
                    const int lj = wn * 32 + nt * 8 + tig * 2;
                    if (lj > rl)     p0 = 0.f;
                    if (lj + 1 > rl) p1 = 0.f;
                }
                *(float2*)(prow + nt * 8 + tig * 2) = make_float2(p0, p1);
                uint2 pt; pt.x = cvt_tf32(p0); pt.y = cvt_tf32(p1);
                *(uint2*)(psrow + nt * 8 + tig * 2) = pt;
            }
        }
        cp_wait(jt < it ? 1 : 0);
        __syncthreads();

        // ctx += P @ V^T-chunk
#pragma unroll
        for (int kp = 0; kp < 4; kp++) {
            uint32_t bF[4][4];
#pragma unroll
            for (int nt = 0; nt < 4; nt++) ldsm4(bF[nt], bV + nt * (8 * FSTR * 4) + kp * 64);
#pragma unroll
            for (int k2 = 0; k2 < 2; k2++) {
                uint32_t aF[4];
                ldsm4(aF, aP + (kp * 2 + k2) * 32);
#pragma unroll
                for (int nt = 0; nt < 4; nt++)
                    mma8(cacc[nt], aF, bF[nt][k2 * 2], bF[nt][k2 * 2 + 1]);
            }
        }
        __syncthreads();
    }

    // ctx epilogue: [b,s,h,d] == [B,S,E]
    const int b = bh >> 4, hh = bh & 15;
    const int s0 = it * 64 + wm * 16 + gid;
#pragma unroll
    for (int nt = 0; nt < 4; nt++) {
        const int d0 = wn * 32 + nt * 8 + tig * 2;
        *(float2*)&ctx[((size_t)(b * S + s0)) * E + hh * D + d0] =
            make_float2(cacc[nt][0], cacc[nt][1]);
        *(float2*)&ctx[((size_t)(b * S + s0 + 8)) * E + hh * D + d0] =
            make_float2(cacc[nt][2], cacc[nt][3]);
    }

    // zero-fill columns beyond the causal edge
    const int zc0 = (it + 1) * 64;
    if (zc0 < S) {
        const int r = tid >> 2;
        float* row = attn + ((size_t)bh * S + it * 64 + r) * S;
        const float4 z = make_float4(0.f, 0.f, 0.f, 0.f);
        for (int c = zc0 + (tid & 3) * 4; c < S; c += 16)
            *(float4*)(row + c) = z;
    }
}

// ============================================================
// launch
// ============================================================
extern "C" void kernel_launch(void* const* d_in, const int* in_sizes, int n_in,
                              void* d_out_v, int out_size)
{
    const float* query = (const float*)d_in[0];
    const float* key_  = (const float*)d_in[1];
    const float* value = (const float*)d_in[2];
    const float* Wq = (const float*)d_in[4];
    const float* bq = (const float*)d_in[5];
    const float* Wk = (const float*)d_in[6];
    const float* bk = (const float*)d_in[7];
    const float* Wv = (const float*)d_in[8];
    const float* bv = (const float*)d_in[9];
    const float* Wo = (const float*)d_in[10];
    const float* bo = (const float*)d_in[11];
    float* d_out = (float*)d_out_v;

    float *qp, *kp, *vtp, *cp, *op, *ap;
    cudaGetSymbolAddress((void**)&qp,  g_q);
    cudaGetSymbolAddress((void**)&kp,  g_k);
    cudaGetSymbolAddress((void**)&vtp, g_vt);
    cudaGetSymbolAddress((void**)&cp,  g_ctx);
    cudaGetSymbolAddress((void**)&op,  g_out);
    cudaGetSymbolAddress((void**)&ap,  g_attn);

    float* out_ptr;
    float* attn_ptr;
    long long osz = (long long)out_size;
    if (osz >= (long long)OUT_N + (long long)ATT_N) {
        out_ptr = d_out; attn_ptr = d_out + OUT_N;
    } else if (osz == (long long)OUT_N) {
        out_ptr = d_out; attn_ptr = ap;
    } else {
        attn_ptr = d_out; out_ptr = op;
    }

    const int FUSED_SMEM = (5 * 64 * FSTR + 384) * 4;   // ~88.6 KB
    cudaFuncSetAttribute(fused_attn, cudaFuncAttributeMaxDynamicSharedMemorySize,
                         FUSED_SMEM);

    dim3 gP(E / 128, M_ROWS / 128);
    gemm_tf32<1><<<gP, 256>>>(query, Wq, bq, qp,  E);
    gemm_tf32<1><<<gP, 256>>>(key_,  Wk, bk, kp,  E);
    gemm_tf32<2><<<gP, 256>>>(value, Wv, bv, vtp, E);

    dim3 gF(Bn * H, 32);
    fused_attn<<<gF, 256, FUSED_SMEM>>>(qp, kp, vtp, attn_ptr, cp);

    gemm_tf32<0><<<gP, 256>>>(cp, Wo, bo, out_ptr, E);
}

// round 6
// speedup vs baseline: 3.2032x; 1.0268x over previous
#include <cuda_runtime.h>
#include <cstdint>

// ---------------- problem constants ----------------
#define S   2048
#define E   1024
#define H   16
#define D   64
#define Bn  2
#define M_ROWS (Bn * S)
#define OUT_N  (Bn * S * E)
#define ATT_N  (134217728)
#define GSTR 20      // gemm smem stride (words)
#define FSTR 68      // fused smem stride (words)

// ---------------- device scratch ----------------
__device__ float g_q[Bn * H * S * D];
__device__ float g_k[Bn * H * S * D];
__device__ float g_vt[Bn * H * D * S];   // V transposed: [b,h,d,s]
__device__ float g_ctx[Bn * S * E];
__device__ float g_out[OUT_N];
__device__ float g_attn[ATT_N];

// ---------------- helpers ----------------
__device__ __forceinline__ uint32_t cvt_tf32(float x) {
    uint32_t u; asm("cvt.rna.tf32.f32 %0, %1;" : "=r"(u) : "f"(x)); return u;
}
__device__ __forceinline__ void sts4(uint32_t* p, float4 v) {
    uint4 u; u.x = cvt_tf32(v.x); u.y = cvt_tf32(v.y);
    u.z = cvt_tf32(v.z); u.w = cvt_tf32(v.w);
    *(uint4*)p = u;
}
__device__ __forceinline__ void ldsm4(uint32_t r[4], uint32_t addr) {
    asm volatile("ldmatrix.sync.aligned.m8n8.x4.shared.b16 {%0,%1,%2,%3}, [%4];"
        : "=r"(r[0]), "=r"(r[1]), "=r"(r[2]), "=r"(r[3]) : "r"(addr));
}
__device__ __forceinline__ void mma8(float c[4], const uint32_t a[4],
                                     uint32_t b0, uint32_t b1) {
    asm volatile("mma.sync.aligned.m16n8k8.row.col.f32.tf32.tf32.f32 "
        "{%0,%1,%2,%3},{%4,%5,%6,%7},{%8,%9},{%0,%1,%2,%3};"
        : "+f"(c[0]), "+f"(c[1]), "+f"(c[2]), "+f"(c[3])
        : "r"(a[0]), "r"(a[1]), "r"(a[2]), "r"(a[3]), "r"(b0), "r"(b1));
}
__device__ __forceinline__ void cpa16(uint32_t dst, const float* src) {
    asm volatile("cp.async.ca.shared.global [%0], [%1], 16;" :: "r"(dst), "l"(src));
}
__device__ __forceinline__ void cp_commit() {
    asm volatile("cp.async.commit_group;");
}
__device__ __forceinline__ void cp_wait0() {
    asm volatile("cp.async.wait_group 0;");
}

// ============================================================
// GEMM: out = A[M,K] @ W[N,K]^T + bias  (tf32, double-buffered)
// ============================================================
template<int MODE>
__global__ __launch_bounds__(256, 2) void gemm_tf32(
    const float* __restrict__ A, const float* __restrict__ W,
    const float* __restrict__ bias, float* __restrict__ out, int K)
{
    __shared__ uint32_t As[2][128 * GSTR];
    __shared__ uint32_t Ws[2][128 * GSTR];
    const int tid = threadIdx.x, lane = tid & 31, warp = tid >> 5;
    const int rowBase = blockIdx.y * 128, colBase = blockIdx.x * 128;
    const int lr = tid >> 1, lk = (tid & 1) * 8;

    const float* Ap = A + (size_t)(rowBase + lr) * K + lk;
    const float* Wp = W + (size_t)(colBase + lr) * K + lk;
    float4 ra0 = *(const float4*)Ap, ra1 = *(const float4*)(Ap + 4);
    float4 rw0 = *(const float4*)Wp, rw1 = *(const float4*)(Wp + 4);

    float acc[4][4][4];
#pragma unroll
    for (int i = 0; i < 4; i++)
#pragma unroll
        for (int j = 0; j < 4; j++)
#pragma unroll
            for (int l = 0; l < 4; l++) acc[i][j][l] = 0.f;

    const int wm = warp & 1, wn = warp >> 1;
    const int asub = lane >> 3, ar = lane & 7;
    const uint32_t sA = (uint32_t)__cvta_generic_to_shared(&As[0][0]);
    const uint32_t sW = (uint32_t)__cvta_generic_to_shared(&Ws[0][0]);
    const uint32_t aOff = (((wm * 64 + ar + (asub & 1) * 8) * GSTR + (asub >> 1) * 4) << 2);
    const uint32_t bOff = (((wn * 32 + ar) * GSTR + asub * 4) << 2);
    const uint32_t bufBytes = 128 * GSTR * 4;

    sts4(&As[0][lr * GSTR + lk], ra0); sts4(&As[0][lr * GSTR + lk + 4], ra1);
    sts4(&Ws[0][lr * GSTR + lk], rw0); sts4(&Ws[0][lr * GSTR + lk + 4], rw1);
    __syncthreads();

    for (int kk = 0; kk < K; kk += 16) {
        const int cur = (kk >> 4) & 1;
        const bool more = (kk + 16 < K);
        if (more) {
            ra0 = *(const float4*)(Ap + kk + 16); ra1 = *(const float4*)(Ap + kk + 20);
            rw0 = *(const float4*)(Wp + kk + 16); rw1 = *(const float4*)(Wp + kk + 20);
        }
        const uint32_t aAddr = sA + cur * bufBytes + aOff;
        const uint32_t bAddr = sW + cur * bufBytes + bOff;
        uint32_t bF[4][4];
#pragma unroll
        for (int nt = 0; nt < 4; nt++) ldsm4(bF[nt], bAddr + nt * (8 * GSTR * 4));
#pragma unroll
        for (int ks = 0; ks < 2; ks++) {
            uint32_t aF[4][4];
#pragma unroll
            for (int mt = 0; mt < 4; mt++) ldsm4(aF[mt], aAddr + mt * (16 * GSTR * 4) + ks * 32);
#pragma unroll
            for (int mt = 0; mt < 4; mt++)
#pragma unroll
                for (int nt = 0; nt < 4; nt++)
                    mma8(acc[mt][nt], aF[mt], bF[nt][ks * 2], bF[nt][ks * 2 + 1]);
        }
        if (more) {
            const int nxt = cur ^ 1;
            sts4(&As[nxt][lr * GSTR + lk], ra0); sts4(&As[nxt][lr * GSTR + lk + 4], ra1);
            sts4(&Ws[nxt][lr * GSTR + lk], rw0); sts4(&Ws[nxt][lr * GSTR + lk + 4], rw1);
        }
        __syncthreads();
    }

    const int gid = lane >> 2, tig = lane & 3;
#pragma unroll
    for (int nt = 0; nt < 4; nt++) {
        const int col0 = colBase + wn * 32 + nt * 8 + tig * 2;
        const float bb0 = bias[col0], bb1 = bias[col0 + 1];
#pragma unroll
        for (int mt = 0; mt < 4; mt++) {
            const int row0 = rowBase + wm * 64 + mt * 16 + gid;
            float v00 = acc[mt][nt][0] + bb0, v01 = acc[mt][nt][1] + bb1;
            float v10 = acc[mt][nt][2] + bb0, v11 = acc[mt][nt][3] + bb1;
            if (MODE != 0) {
                v00 = __uint_as_float(cvt_tf32(v00));
                v01 = __uint_as_float(cvt_tf32(v01));
                v10 = __uint_as_float(cvt_tf32(v10));
                v11 = __uint_as_float(cvt_tf32(v11));
            }
            if (MODE == 0) {
                *(float2*)&out[(size_t)row0 * E + col0]       = make_float2(v00, v01);
                *(float2*)&out[(size_t)(row0 + 8) * E + col0] = make_float2(v10, v11);
            } else if (MODE == 1) {
                const int b = row0 >> 11, s0 = row0 & (S - 1);
                const int h = col0 >> 6, d0 = col0 & 63;
                const size_t base = ((size_t)(b * H + h)) * S;
                *(float2*)&out[(base + s0) * D + d0]     = make_float2(v00, v01);
                *(float2*)&out[(base + s0 + 8) * D + d0] = make_float2(v10, v11);
            } else {
                const int b = row0 >> 11, s0 = row0 & (S - 1);
                const int h = col0 >> 6, d0 = col0 & 63;
                const size_t base = ((size_t)(b * H + h)) * D;
                out[(base + d0) * S + s0]         = v00;
                out[(base + d0 + 1) * S + s0]     = v01;
                out[(base + d0) * S + s0 + 8]     = v10;
                out[(base + d0 + 1) * S + s0 + 8] = v11;
            }
        }
    }
}

// ============================================================
// Fused attention, no-max softmax (scores statically bounded).
// Pass1: 1 sync/tile, Z in registers. Pass2: 2 syncs/tile.
// ============================================================
extern __shared__ char fsm[];

__device__ __forceinline__ void scores_tile64(uint32_t aQ, uint32_t kb,
                                              float as[4][4]) {
#pragma unroll
    for (int nt = 0; nt < 4; nt++)
#pragma unroll
        for (int c = 0; c < 4; c++) as[nt][c] = 0.f;
#pragma unroll
    for (int kp = 0; kp < 4; kp++) {
        uint32_t bF[4][4];
#pragma unroll
        for (int nt = 0; nt < 4; nt++) ldsm4(bF[nt], kb + nt * (8 * FSTR * 4) + kp * 64);
#pragma unroll
        for (int k2 = 0; k2 < 2; k2++) {
            uint32_t aF[4];
            ldsm4(aF, aQ + (kp * 2 + k2) * 32);
#pragma unroll
            for (int nt = 0; nt < 4; nt++)
                mma8(as[nt], aF, bF[nt][k2 * 2], bF[nt][k2 * 2 + 1]);
        }
    }
}

__global__ __launch_bounds__(256, 2) void fused_attn(
    const float* __restrict__ q, const float* __restrict__ k,
    const float* __restrict__ vt, float* __restrict__ attn,
    float* __restrict__ ctx)
{
    const int bh = blockIdx.x;
    const int it = 31 - blockIdx.y;
    const int tid = threadIdx.x, lane = tid & 31, warp = tid >> 5;
    const int wm = warp & 3, wn = warp >> 2;
    const int gid = lane >> 2, tig = lane & 3;
    const int asub = lane >> 3, ar = lane & 7;

    float* Qs   = (float*)fsm;               // 64*FSTR
    float* Ks   = Qs + 64 * FSTR;            // 2 x 64*FSTR
    float* Vs   = Ks + 2 * 64 * FSTR;        // 2 x 64*FSTR
    float* Ps   = Vs + 2 * 64 * FSTR;        // 64*FSTR
    float* Zred = Ps + 64 * FSTR;            // [64][2]

    const uint32_t sQ = (uint32_t)__cvta_generic_to_shared(Qs);
    const uint32_t sK = (uint32_t)__cvta_generic_to_shared(Ks);
    const uint32_t sV = (uint32_t)__cvta_generic_to_shared(Vs);
    const uint32_t sP = (uint32_t)__cvta_generic_to_shared(Ps);
    const uint32_t bufB = 64 * FSTR * 4;

    const int l_r = tid >> 2, l_c = tid & 3;     // 64x64 loader

    const float* qbase  = q + ((size_t)bh * S + (size_t)it * 64) * D;
    const float* kbase0 = k + (size_t)bh * S * D;
    const float* vbase  = vt + ((size_t)bh * D + l_r) * S + l_c * 4;

    const uint32_t aQ   = sQ + (((wm * 16 + ar + (asub & 1) * 8) * FSTR + (asub >> 1) * 4) << 2);
    const uint32_t kOff = (((wn * 32 + ar) * FSTR + asub * 4) << 2);
    const uint32_t aP   = sP + (((wm * 16 + ar + (asub & 1) * 8) * FSTR + (asub >> 1) * 4) << 2);
    const uint32_t vOff = (((wn * 32 + ar) * FSTR + asub * 4) << 2);
    const uint32_t ldOff = ((l_r * FSTR + l_c * 4) << 2);
    const float*   ldSrcK = kbase0 + (size_t)l_r * 64 + l_c * 4;

    // ---- prologue: Q group, K0 group ----
#pragma unroll
    for (int i = 0; i < 4; i++)
        cpa16(sQ + ldOff + (i << 6), qbase + l_r * 64 + l_c * 4 + i * 16);
    cp_commit();
#pragma unroll
    for (int i = 0; i < 4; i++)
        cpa16(sK + ldOff + (i << 6), ldSrcK + i * 16);
    cp_commit();

    float as[4][4];
    float Zacc[2] = {0.f, 0.f};

    // =================== PASS 1: Z only, registers ===================
    for (int jt = 0; jt <= it; jt++) {
        cp_wait0();
        __syncthreads();                       // data visible + prev compute done
        if (jt < it) {
#pragma unroll
            for (int i = 0; i < 4; i++)
                cpa16(sK + ((jt + 1) & 1) * bufB + ldOff + (i << 6),
                      ldSrcK + (size_t)(jt + 1) * 64 * D + i * 16);
            cp_commit();
        }
        scores_tile64(aQ, sK + (jt & 1) * bufB + kOff, as);

        const bool diag = (jt == it);
#pragma unroll
        for (int h = 0; h < 2; h++) {
            const int li = wm * 16 + gid + h * 8;
            float z = 0.f;
#pragma unroll
            for (int nt = 0; nt < 4; nt++) {
                const int lj = wn * 32 + nt * 8 + tig * 2;
                float e0 = __expf(as[nt][h * 2]     * 0.125f);
                float e1 = __expf(as[nt][h * 2 + 1] * 0.125f);
                if (diag) { if (lj > li) e0 = 0.f; if (lj + 1 > li) e1 = 0.f; }
                z += e0 + e1;
            }
            Zacc[h] += z;
        }
    }

    // cross-lane + cross-warp Z reduction (once per stripe)
#pragma unroll
    for (int h = 0; h < 2; h++) {
        float z = Zacc[h];
        z += __shfl_xor_sync(0xffffffffu, z, 1);
        z += __shfl_xor_sync(0xffffffffu, z, 2);
        if (tig == 0) Zred[(wm * 16 + gid + h * 8) * 2 + wn] = z;
    }
    __syncthreads();                            // Zred ready; all K reads done

    // pass-2 prologue: joint {K0, V0} group (issued after the sync above)
#pragma unroll
    for (int i = 0; i < 4; i++)
        cpa16(sK + ldOff + (i << 6), ldSrcK + i * 16);
#pragma unroll
    for (int i = 0; i < 4; i++)
        cpa16(sV + ldOff + (i << 6), vbase + i * 16);
    cp_commit();

    float Zi[2];
#pragma unroll
    for (int h = 0; h < 2; h++) {
        const int r = wm * 16 + gid + h * 8;
        Zi[h] = 1.f / (Zred[r * 2] + Zred[r * 2 + 1]);
    }

    // =================== PASS 2: p + P@V ===================
    float cacc[4][4];
#pragma unroll
    for (int nt = 0; nt < 4; nt++)
#pragma unroll
        for (int c = 0; c < 4; c++) cacc[nt][c] = 0.f;

    for (int jt = 0; jt <= it; jt++) {
        cp_wait0();
        __syncthreads();                       // K,V visible; prev P@V done
        if (jt < it) {
#pragma unroll
            for (int i = 0; i < 4; i++)
                cpa16(sK + ((jt + 1) & 1) * bufB + ldOff + (i << 6),
                      ldSrcK + (size_t)(jt + 1) * 64 * D + i * 16);
#pragma unroll
            for (int i = 0; i < 4; i++)
                cpa16(sV + ((jt + 1) & 1) * bufB + ldOff + (i << 6),
                      vbase + (size_t)(jt + 1) * 64 + i * 16);
            cp_commit();
        }
        scores_tile64(aQ, sK + (jt & 1) * bufB + kOff, as);

        const bool diag = (jt == it);
#pragma unroll
        for (int h = 0; h < 2; h++) {
            const int rl = wm * 16 + gid + h * 8;
            const int gi = it * 64 + rl;
            float* prow = attn + ((size_t)bh * S + gi) * S + jt * 64 + wn * 32;
            uint32_t* psrow = (uint32_t*)Ps + rl * FSTR + wn * 32;
#pragma unroll
            for (int nt = 0; nt < 4; nt++) {
                float p0 = __expf(as[nt][h * 2]     * 0.125f) * Zi[h];
                float p1 = __expf(as[nt][h * 2 + 1] * 0.125f) * Zi[h];
                if (diag) {
                    const int lj = wn * 32 + nt * 8 + tig * 2;
                    if (lj > rl)     p0 = 0.f;
                    if (lj + 1 > rl) p1 = 0.f;
                }
                *(float2*)(prow + nt * 8 + tig * 2) = make_float2(p0, p1);
                uint2 pt; pt.x = cvt_tf32(p0); pt.y = cvt_tf32(p1);
                *(uint2*)(psrow + nt * 8 + tig * 2) = pt;
            }
        }
        __syncthreads();                       // P staged for all warps

        const uint32_t bV = sV + (jt & 1) * bufB + vOff;
#pragma unroll
        for (int kp = 0; kp < 4; kp++) {
            uint32_t bF[4][4];
#pragma unroll
            for (int nt = 0; nt < 4; nt++) ldsm4(bF[nt], bV + nt * (8 * FSTR * 4) + kp * 64);
#pragma unroll
            for (int k2 = 0; k2 < 2; k2++) {
                uint32_t aF[4];
                ldsm4(aF, aP + (kp * 2 + k2) * 32);
#pragma unroll
                for (int nt = 0; nt < 4; nt++)
                    mma8(cacc[nt], aF, bF[nt][k2 * 2], bF[nt][k2 * 2 + 1]);
            }
        }
    }
    __syncthreads();

    // ctx epilogue: [b,s,h,d] == [B,S,E]
    const int b = bh >> 4, hh = bh & 15;
    const int s0 = it * 64 + wm * 16 + gid;
#pragma unroll
    for (int nt = 0; nt < 4; nt++) {
        const int d0 = wn * 32 + nt * 8 + tig * 2;
        *(float2*)&ctx[((size_t)(b * S + s0)) * E + hh * D + d0] =
            make_float2(cacc[nt][0], cacc[nt][1]);
        *(float2*)&ctx[((size_t)(b * S + s0 + 8)) * E + hh * D + d0] =
            make_float2(cacc[nt][2], cacc[nt][3]);
    }

    // zero-fill columns beyond the causal edge
    const int zc0 = (it + 1) * 64;
    if (zc0 < S) {
        const int r = tid >> 2;
        float* row = attn + ((size_t)bh * S + it * 64 + r) * S;
        const float4 z = make_float4(0.f, 0.f, 0.f, 0.f);
        for (int c = zc0 + (tid & 3) * 4; c < S; c += 16)
            *(float4*)(row + c) = z;
    }
}

// ============================================================
// launch
// ============================================================
extern "C" void kernel_launch(void* const* d_in, const int* in_sizes, int n_in,
                              void* d_out_v, int out_size)
{
    const float* query = (const float*)d_in[0];
    const float* key_  = (const float*)d_in[1];
    const float* value = (const float*)d_in[2];
    const float* Wq = (const float*)d_in[4];
    const float* bq = (const float*)d_in[5];
    const float* Wk = (const float*)d_in[6];
    const float* bk = (const float*)d_in[7];
    const float* Wv = (const float*)d_in[8];
    const float* bv = (const float*)d_in[9];
    const float* Wo = (const float*)d_in[10];
    const float* bo = (const float*)d_in[11];
    float* d_out = (float*)d_out_v;

    float *qp, *kp, *vtp, *cp, *op, *ap;
    cudaGetSymbolAddress((void**)&qp,  g_q);
    cudaGetSymbolAddress((void**)&kp,  g_k);
    cudaGetSymbolAddress((void**)&vtp, g_vt);
    cudaGetSymbolAddress((void**)&cp,  g_ctx);
    cudaGetSymbolAddress((void**)&op,  g_out);
    cudaGetSymbolAddress((void**)&ap,  g_attn);

    float* out_ptr;
    float* attn_ptr;
    long long osz = (long long)out_size;
    if (osz >= (long long)OUT_N + (long long)ATT_N) {
        out_ptr = d_out; attn_ptr = d_out + OUT_N;
    } else if (osz == (long long)OUT_N) {
        out_ptr = d_out; attn_ptr = ap;
    } else {
        attn_ptr = d_out; out_ptr = op;
    }

    const int FUSED_SMEM = (6 * 64 * FSTR + 192) * 4;   // ~105 KB
    cudaFuncSetAttribute(fused_attn, cudaFuncAttributeMaxDynamicSharedMemorySize,
                         FUSED_SMEM);

    dim3 gP(E / 128, M_ROWS / 128);
    gemm_tf32<1><<<gP, 256>>>(query, Wq, bq, qp,  E);
    gemm_tf32<1><<<gP, 256>>>(key_,  Wk, bk, kp,  E);
    gemm_tf32<2><<<gP, 256>>>(value, Wv, bv, vtp, E);

    dim3 gF(Bn * H, 32);
    fused_attn<<<gF, 256, FUSED_SMEM>>>(qp, kp, vtp, attn_ptr, cp);

    gemm_tf32<0><<<gP, 256>>>(cp, Wo, bo, out_ptr, E);
}

// round 7
// speedup vs baseline: 3.2696x; 1.0207x over previous
#include <cuda_runtime.h>
#include <cstdint>

// ---------------- problem constants ----------------
#define S   2048
#define E   1024
#define H   16
#define D   64
#define Bn  2
#define M_ROWS (Bn * S)
#define OUT_N  (Bn * S * E)
#define ATT_N  (134217728)
#define GSTR 20      // gemm smem stride (words)
#define FSTR 68      // fused smem stride (words)

// ---------------- device scratch ----------------
__device__ float g_q[Bn * H * S * D];
__device__ float g_k[Bn * H * S * D];
__device__ float g_vt[Bn * H * D * S];   // V transposed: [b,h,d,s]
__device__ float g_ctx[Bn * S * E];
__device__ float g_out[OUT_N];
__device__ float g_attn[ATT_N];

// ---------------- helpers ----------------
__device__ __forceinline__ uint32_t cvt_tf32(float x) {
    uint32_t u; asm("cvt.rna.tf32.f32 %0, %1;" : "=r"(u) : "f"(x)); return u;
}
__device__ __forceinline__ void sts4(uint32_t* p, float4 v) {
    uint4 u; u.x = cvt_tf32(v.x); u.y = cvt_tf32(v.y);
    u.z = cvt_tf32(v.z); u.w = cvt_tf32(v.w);
    *(uint4*)p = u;
}
__device__ __forceinline__ void ldsm4(uint32_t r[4], uint32_t addr) {
    asm volatile("ldmatrix.sync.aligned.m8n8.x4.shared.b16 {%0,%1,%2,%3}, [%4];"
        : "=r"(r[0]), "=r"(r[1]), "=r"(r[2]), "=r"(r[3]) : "r"(addr));
}
__device__ __forceinline__ void mma8(float c[4], const uint32_t a[4],
                                     uint32_t b0, uint32_t b1) {
    asm volatile("mma.sync.aligned.m16n8k8.row.col.f32.tf32.tf32.f32 "
        "{%0,%1,%2,%3},{%4,%5,%6,%7},{%8,%9},{%0,%1,%2,%3};"
        : "+f"(c[0]), "+f"(c[1]), "+f"(c[2]), "+f"(c[3])
        : "r"(a[0]), "r"(a[1]), "r"(a[2]), "r"(a[3]), "r"(b0), "r"(b1));
}
__device__ __forceinline__ void cpa16(uint32_t dst, const float* src) {
    asm volatile("cp.async.ca.shared.global [%0], [%1], 16;" :: "r"(dst), "l"(src));
}
__device__ __forceinline__ void cp_commit() {
    asm volatile("cp.async.commit_group;");
}
__device__ __forceinline__ void cp_wait0() {
    asm volatile("cp.async.wait_group 0;");
}

// ============================================================
// GEMM: out = A[M,K] @ W[N,K]^T + bias  (tf32, double-buffered)
// ============================================================
template<int MODE>
__global__ __launch_bounds__(256, 2) void gemm_tf32(
    const float* __restrict__ A, const float* __restrict__ W,
    const float* __restrict__ bias, float* __restrict__ out, int K)
{
    __shared__ uint32_t As[2][128 * GSTR];
    __shared__ uint32_t Ws[2][128 * GSTR];
    const int tid = threadIdx.x, lane = tid & 31, warp = tid >> 5;
    const int rowBase = blockIdx.y * 128, colBase = blockIdx.x * 128;
    const int lr = tid >> 1, lk = (tid & 1) * 8;

    const float* Ap = A + (size_t)(rowBase + lr) * K + lk;
    const float* Wp = W + (size_t)(colBase + lr) * K + lk;
    float4 ra0 = *(const float4*)Ap, ra1 = *(const float4*)(Ap + 4);
    float4 rw0 = *(const float4*)Wp, rw1 = *(const float4*)(Wp + 4);

    float acc[4][4][4];
#pragma unroll
    for (int i = 0; i < 4; i++)
#pragma unroll
        for (int j = 0; j < 4; j++)
#pragma unroll
            for (int l = 0; l < 4; l++) acc[i][j][l] = 0.f;

    const int wm = warp & 1, wn = warp >> 1;
    const int asub = lane >> 3, ar = lane & 7;
    const uint32_t sA = (uint32_t)__cvta_generic_to_shared(&As[0][0]);
    const uint32_t sW = (uint32_t)__cvta_generic_to_shared(&Ws[0][0]);
    const uint32_t aOff = (((wm * 64 + ar + (asub & 1) * 8) * GSTR + (asub >> 1) * 4) << 2);
    const uint32_t bOff = (((wn * 32 + ar) * GSTR + asub * 4) << 2);
    const uint32_t bufBytes = 128 * GSTR * 4;

    sts4(&As[0][lr * GSTR + lk], ra0); sts4(&As[0][lr * GSTR + lk + 4], ra1);
    sts4(&Ws[0][lr * GSTR + lk], rw0); sts4(&Ws[0][lr * GSTR + lk + 4], rw1);
    __syncthreads();

    for (int kk = 0; kk < K; kk += 16) {
        const int cur = (kk >> 4) & 1;
        const bool more = (kk + 16 < K);
        if (more) {
            ra0 = *(const float4*)(Ap + kk + 16); ra1 = *(const float4*)(Ap + kk + 20);
            rw0 = *(const float4*)(Wp + kk + 16); rw1 = *(const float4*)(Wp + kk + 20);
        }
        const uint32_t aAddr = sA + cur * bufBytes + aOff;
        const uint32_t bAddr = sW + cur * bufBytes + bOff;
        uint32_t bF[4][4];
#pragma unroll
        for (int nt = 0; nt < 4; nt++) ldsm4(bF[nt], bAddr + nt * (8 * GSTR * 4));
#pragma unroll
        for (int ks = 0; ks < 2; ks++) {
            uint32_t aF[4][4];
#pragma unroll
            for (int mt = 0; mt < 4; mt++) ldsm4(aF[mt], aAddr + mt * (16 * GSTR * 4) + ks * 32);
#pragma unroll
            for (int mt = 0; mt < 4; mt++)
#pragma unroll
                for (int nt = 0; nt < 4; nt++)
                    mma8(acc[mt][nt], aF[mt], bF[nt][ks * 2], bF[nt][ks * 2 + 1]);
        }
        if (more) {
            const int nxt = cur ^ 1;
            sts4(&As[nxt][lr * GSTR + lk], ra0); sts4(&As[nxt][lr * GSTR + lk + 4], ra1);
            sts4(&Ws[nxt][lr * GSTR + lk], rw0); sts4(&Ws[nxt][lr * GSTR + lk + 4], rw1);
        }
        __syncthreads();
    }

    const int gid = lane >> 2, tig = lane & 3;
#pragma unroll
    for (int nt = 0; nt < 4; nt++) {
        const int col0 = colBase + wn * 32 + nt * 8 + tig * 2;
        const float bb0 = bias[col0], bb1 = bias[col0 + 1];
#pragma unroll
        for (int mt = 0; mt < 4; mt++) {
            const int row0 = rowBase + wm * 64 + mt * 16 + gid;
            float v00 = acc[mt][nt][0] + bb0, v01 = acc[mt][nt][1] + bb1;
            float v10 = acc[mt][nt][2] + bb0, v11 = acc[mt][nt][3] + bb1;
            if (MODE != 0) {
                v00 = __uint_as_float(cvt_tf32(v00));
                v01 = __uint_as_float(cvt_tf32(v01));
                v10 = __uint_as_float(cvt_tf32(v10));
                v11 = __uint_as_float(cvt_tf32(v11));
            }
            if (MODE == 0) {
                *(float2*)&out[(size_t)row0 * E + col0]       = make_float2(v00, v01);
                *(float2*)&out[(size_t)(row0 + 8) * E + col0] = make_float2(v10, v11);
            } else if (MODE == 1) {
                const int b = row0 >> 11, s0 = row0 & (S - 1);
                const int h = col0 >> 6, d0 = col0 & 63;
                const size_t base = ((size_t)(b * H + h)) * S;
                *(float2*)&out[(base + s0) * D + d0]     = make_float2(v00, v01);
                *(float2*)&out[(base + s0 + 8) * D + d0] = make_float2(v10, v11);
            } else {
                const int b = row0 >> 11, s0 = row0 & (S - 1);
                const int h = col0 >> 6, d0 = col0 & 63;
                const size_t base = ((size_t)(b * H + h)) * D;
                out[(base + d0) * S + s0]         = v00;
                out[(base + d0 + 1) * S + s0]     = v01;
                out[(base + d0) * S + s0 + 8]     = v10;
                out[(base + d0 + 1) * S + s0 + 8] = v11;
            }
        }
    }
}

// ============================================================
// Fused attention: 128-row stripe, warp-owned 16-row slices.
// Q in registers; stats warp-local; 1 block barrier per tile.
// ============================================================
extern __shared__ char fsm[];

__global__ __launch_bounds__(256, 2) void fused_attn(
    const float* __restrict__ q, const float* __restrict__ k,
    const float* __restrict__ vt, float* __restrict__ attn,
    float* __restrict__ ctx)
{
    const int bh = blockIdx.x;
    const int it = 15 - blockIdx.y;          // 16 stripes of 128 rows, big-first
    const int nj = 2 * (it + 1);             // 64-col tiles in causal prefix
    const int tid = threadIdx.x, lane = tid & 31, w = tid >> 5;
    const int gid = lane >> 2, tig = lane & 3;
    const int asub = lane >> 3, ar = lane & 7;

    float* QP = (float*)fsm;                 // 128*FSTR (Q staging, then P)
    float* Ks = QP + 128 * FSTR;             // 2 x 64*FSTR
    float* Vs = Ks + 2 * 64 * FSTR;          // 2 x 64*FSTR

    const uint32_t sQP = (uint32_t)__cvta_generic_to_shared(QP);
    const uint32_t sK  = (uint32_t)__cvta_generic_to_shared(Ks);
    const uint32_t sV  = (uint32_t)__cvta_generic_to_shared(Vs);
    const uint32_t bufB = 64 * FSTR * 4;

    // loaders
    const int lq_r = tid >> 1, lq_c = (tid & 1) * 32;   // Q: 128x64
    const int lk_r = tid >> 2, lk_c = (tid & 3) * 4;    // K/V: 64x64

    const float* qbase = q + ((size_t)bh * S + (size_t)it * 128) * D;
    const float* kbase = k + (size_t)bh * S * D;
    const float* vbase = vt + ((size_t)bh * D + lk_r) * S + lk_c;

    // ldsm bases: A-frags from QP (rows w*16..), B-frags from K/V
    const uint32_t aAddr = sQP + (((w * 16 + ar + (asub & 1) * 8) * FSTR + (asub >> 1) * 4) << 2);
    const uint32_t bOff  = ((ar * FSTR + asub * 4) << 2);

    // ---- prologue: stage Q, prefetch K0, load Q into registers ----
#pragma unroll
    for (int i = 0; i < 8; i++)
        cpa16(sQP + ((lq_r * FSTR + lq_c + i * 4) << 2),
              qbase + lq_r * 64 + lq_c + i * 4);
    cp_commit();
#pragma unroll
    for (int i = 0; i < 4; i++)
        cpa16(sK + ((lk_r * FSTR + lk_c + i * 16) << 2),
              kbase + (size_t)lk_r * 64 + lk_c + i * 16);
    cp_commit();
    cp_wait0();
    __syncthreads();

    uint32_t aQ[8][4];
#pragma unroll
    for (int c = 0; c < 8; c++) ldsm4(aQ[c], aAddr + c * 32);
    __syncthreads();                          // Q regs loaded; QP reusable later

    float as[8][4];
    float Zacc[2] = {0.f, 0.f};

    // =================== PASS 1: Z (warp-local, registers) ===================
    for (int jt = 0; jt < nj; jt++) {
        const uint32_t kb = sK + (jt & 1) * bufB + bOff;
        if (jt + 1 < nj) {
#pragma unroll
            for (int i = 0; i < 4; i++)
                cpa16(sK + ((jt + 1) & 1) * bufB + ((lk_r * FSTR + lk_c + i * 16) << 2),
                      kbase + (size_t)((jt + 1) * 64 + lk_r) * 64 + lk_c + i * 16);
            cp_commit();
        }
#pragma unroll
        for (int nt = 0; nt < 8; nt++)
#pragma unroll
            for (int c = 0; c < 4; c++) as[nt][c] = 0.f;
#pragma unroll
        for (int kp = 0; kp < 4; kp++) {
#pragma unroll
            for (int nt = 0; nt < 8; nt++) {
                uint32_t bF[4];
                ldsm4(bF, kb + nt * (8 * FSTR * 4) + kp * 64);
                mma8(as[nt], aQ[kp * 2],     bF[0], bF[1]);
                mma8(as[nt], aQ[kp * 2 + 1], bF[2], bF[3]);
            }
        }
        const bool diag = (jt >= 2 * it);
#pragma unroll
        for (int h = 0; h < 2; h++) {
            const int li = it * 128 + w * 16 + gid + h * 8;
            float z = 0.f;
#pragma unroll
            for (int nt = 0; nt < 8; nt++) {
                const int lj = jt * 64 + nt * 8 + tig * 2;
                float e0 = __expf(as[nt][h * 2]     * 0.125f);
                float e1 = __expf(as[nt][h * 2 + 1] * 0.125f);
                if (diag) { if (lj > li) e0 = 0.f; if (lj + 1 > li) e1 = 0.f; }
                z += e0 + e1;
            }
            Zacc[h] += z;
        }
        if (jt + 1 < nj) { cp_wait0(); __syncthreads(); }
    }

    // warp-local Z reduce (cols split across tig only)
    float Zi[2];
#pragma unroll
    for (int h = 0; h < 2; h++) {
        float z = Zacc[h];
        z += __shfl_xor_sync(0xffffffffu, z, 1);
        z += __shfl_xor_sync(0xffffffffu, z, 2);
        Zi[h] = 1.f / z;
    }

    // =================== PASS 2: p + P@V ===================
    __syncthreads();                          // pass-1 reads done; rings reusable
#pragma unroll
    for (int i = 0; i < 4; i++)
        cpa16(sK + ((lk_r * FSTR + lk_c + i * 16) << 2),
              kbase + (size_t)lk_r * 64 + lk_c + i * 16);
#pragma unroll
    for (int i = 0; i < 4; i++)
        cpa16(sV + ((lk_r * FSTR + lk_c + i * 16) << 2), vbase + i * 16);
    cp_commit();
    cp_wait0();
    __syncthreads();

    float cacc[8][4];
#pragma unroll
    for (int nt = 0; nt < 8; nt++)
#pragma unroll
        for (int c = 0; c < 4; c++) cacc[nt][c] = 0.f;

    for (int jt = 0; jt < nj; jt++) {
        const uint32_t kb = sK + (jt & 1) * bufB + bOff;
        const uint32_t vb = sV + (jt & 1) * bufB + bOff;
        if (jt + 1 < nj) {
#pragma unroll
            for (int i = 0; i < 4; i++)
                cpa16(sK + ((jt + 1) & 1) * bufB + ((lk_r * FSTR + lk_c + i * 16) << 2),
                      kbase + (size_t)((jt + 1) * 64 + lk_r) * 64 + lk_c + i * 16);
#pragma unroll
            for (int i = 0; i < 4; i++)
                cpa16(sV + ((jt + 1) & 1) * bufB + ((lk_r * FSTR + lk_c + i * 16) << 2),
                      vbase + (size_t)(jt + 1) * 64 + i * 16);
            cp_commit();
        }
#pragma unroll
        for (int nt = 0; nt < 8; nt++)
#pragma unroll
            for (int c = 0; c < 4; c++) as[nt][c] = 0.f;
#pragma unroll
        for (int kp = 0; kp < 4; kp++) {
#pragma unroll
            for (int nt = 0; nt < 8; nt++) {
                uint32_t bF[4];
                ldsm4(bF, kb + nt * (8 * FSTR * 4) + kp * 64);
                mma8(as[nt], aQ[kp * 2],     bF[0], bF[1]);
                mma8(as[nt], aQ[kp * 2 + 1], bF[2], bF[3]);
            }
        }
        // p = exp(s)/Z ; STG to attn ; STS to warp-private P slice
        const bool diag = (jt >= 2 * it);
#pragma unroll
        for (int h = 0; h < 2; h++) {
            const int rl = w * 16 + gid + h * 8;
            const int gi = it * 128 + rl;
            float* prow = attn + ((size_t)bh * S + gi) * S + jt * 64;
            uint32_t* psrow = (uint32_t*)QP + rl * FSTR;
#pragma unroll
            for (int nt = 0; nt < 8; nt++) {
                const int lj = jt * 64 + nt * 8 + tig * 2;
                float p0 = __expf(as[nt][h * 2]     * 0.125f) * Zi[h];
                float p1 = __expf(as[nt][h * 2 + 1] * 0.125f) * Zi[h];
                if (diag) { if (lj > gi) p0 = 0.f; if (lj + 1 > gi) p1 = 0.f; }
                *(float2*)(prow + nt * 8 + tig * 2) = make_float2(p0, p1);
                uint2 pt; pt.x = cvt_tf32(p0); pt.y = cvt_tf32(p1);
                *(uint2*)(psrow + nt * 8 + tig * 2) = pt;
            }
        }
        __syncwarp();                         // own slice visible to own ldsm

        // ctx += P(16x64) @ V(64x64)
#pragma unroll
        for (int kp = 0; kp < 4; kp++) {
            uint32_t aP0[4], aP1[4];
            ldsm4(aP0, aAddr + (kp * 2) * 32);
            ldsm4(aP1, aAddr + (kp * 2 + 1) * 32);
#pragma unroll
            for (int nt = 0; nt < 8; nt++) {
                uint32_t bF[4];
                ldsm4(bF, vb + nt * (8 * FSTR * 4) + kp * 64);
                mma8(cacc[nt], aP0, bF[0], bF[1]);
                mma8(cacc[nt], aP1, bF[2], bF[3]);
            }
        }
        if (jt + 1 < nj) { cp_wait0(); __syncthreads(); }
    }

    // ctx epilogue: [b,s,h,d] == [B,S,E]
    const int b = bh >> 4, hh = bh & 15;
    const int s0 = it * 128 + w * 16 + gid;
#pragma unroll
    for (int nt = 0; nt < 8; nt++) {
        const int d0 = nt * 8 + tig * 2;
        *(float2*)&ctx[((size_t)(b * S + s0)) * E + hh * D + d0] =
            make_float2(cacc[nt][0], cacc[nt][1]);
        *(float2*)&ctx[((size_t)(b * S + s0 + 8)) * E + hh * D + d0] =
            make_float2(cacc[nt][2], cacc[nt][3]);
    }

    // zero-fill columns beyond the causal edge
    const int zc0 = nj * 64;
    if (zc0 < S) {
        const int r = tid >> 1;
        float* row = attn + ((size_t)bh * S + it * 128 + r) * S;
        const float4 z = make_float4(0.f, 0.f, 0.f, 0.f);
        for (int c = zc0 + (tid & 1) * 4; c < S; c += 8)
            *(float4*)(row + c) = z;
    }
}

// ============================================================
// launch
// ============================================================
extern "C" void kernel_launch(void* const* d_in, const int* in_sizes, int n_in,
                              void* d_out_v, int out_size)
{
    const float* query = (const float*)d_in[0];
    const float* key_  = (const float*)d_in[1];
    const float* value = (const float*)d_in[2];
    const float* Wq = (const float*)d_in[4];
    const float* bq = (const float*)d_in[5];
    const float* Wk = (const float*)d_in[6];
    const float* bk = (const float*)d_in[7];
    const float* Wv = (const float*)d_in[8];
    const float* bv = (const float*)d_in[9];
    const float* Wo = (const float*)d_in[10];
    const float* bo = (const float*)d_in[11];
    float* d_out = (float*)d_out_v;

    float *qp, *kp, *vtp, *cp, *op, *ap;
    cudaGetSymbolAddress((void**)&qp,  g_q);
    cudaGetSymbolAddress((void**)&kp,  g_k);
    cudaGetSymbolAddress((void**)&vtp, g_vt);
    cudaGetSymbolAddress((void**)&cp,  g_ctx);
    cudaGetSymbolAddress((void**)&op,  g_out);
    cudaGetSymbolAddress((void**)&ap,  g_attn);

    float* out_ptr;
    float* attn_ptr;
    long long osz = (long long)out_size;
    if (osz >= (long long)OUT_N + (long long)ATT_N) {
        out_ptr = d_out; attn_ptr = d_out + OUT_N;
    } else if (osz == (long long)OUT_N) {
        out_ptr = d_out; attn_ptr = ap;
    } else {
        attn_ptr = d_out; out_ptr = op;
    }

    const int FUSED_SMEM = (128 * FSTR + 4 * 64 * FSTR) * 4;   // 104448 B
    cudaFuncSetAttribute(fused_attn, cudaFuncAttributeMaxDynamicSharedMemorySize,
                         FUSED_SMEM);

    dim3 gP(E / 128, M_ROWS / 128);
    gemm_tf32<1><<<gP, 256>>>(query, Wq, bq, qp,  E);
    gemm_tf32<1><<<gP, 256>>>(key_,  Wk, bk, kp,  E);
    gemm_tf32<2><<<gP, 256>>>(value, Wv, bv, vtp, E);

    dim3 gF(Bn * H, 16);
    fused_attn<<<gF, 256, FUSED_SMEM>>>(qp, kp, vtp, attn_ptr, cp);

    gemm_tf32<0><<<gP, 256>>>(cp, Wo, bo, out_ptr, E);
}

// round 8
// speedup vs baseline: 4.8108x; 1.4714x over previous
#include <cuda_runtime.h>
#include <cuda_fp16.h>
#include <cstdint>

// ---------------- problem constants ----------------
#define S   2048
#define E   1024
#define H   16
#define D   64
#define Bn  2
#define M_ROWS (Bn * S)
#define OUT_N  (Bn * S * E)
#define ATT_N  (134217728)
#define GST 24      // gemm smem row stride (halves)
#define KST 72      // fused smem row stride (halves)

// ---------------- device scratch ----------------
__device__ __half g_q[Bn * H * S * D];
__device__ __half g_k[Bn * H * S * D];
__device__ __half g_vt[Bn * H * D * S];   // V transposed: [b,h,d,s]
__device__ __half g_ctx[Bn * S * E];
__device__ float  g_out[OUT_N];
__device__ float  g_attn[ATT_N];

// ---------------- helpers ----------------
__device__ __forceinline__ uint32_t f2h2(float a, float b) {
    __half2 h = __floats2half2_rn(a, b);
    return *(uint32_t*)&h;
}
__device__ __forceinline__ void ldsm4(uint32_t r[4], uint32_t addr) {
    asm volatile("ldmatrix.sync.aligned.m8n8.x4.shared.b16 {%0,%1,%2,%3}, [%4];"
        : "=r"(r[0]), "=r"(r[1]), "=r"(r[2]), "=r"(r[3]) : "r"(addr));
}
// m16n8k16 fp16 mma, fp32 accum
__device__ __forceinline__ void mma16(float c[4], const uint32_t a[4],
                                      uint32_t b0, uint32_t b1) {
    asm volatile("mma.sync.aligned.m16n8k16.row.col.f32.f16.f16.f32 "
        "{%0,%1,%2,%3},{%4,%5,%6,%7},{%8,%9},{%0,%1,%2,%3};"
        : "+f"(c[0]), "+f"(c[1]), "+f"(c[2]), "+f"(c[3])
        : "r"(a[0]), "r"(a[1]), "r"(a[2]), "r"(a[3]), "r"(b0), "r"(b1));
}
__device__ __forceinline__ void cpa16(uint32_t dst, const void* src) {
    asm volatile("cp.async.ca.shared.global [%0], [%1], 16;" :: "r"(dst), "l"(src));
}
__device__ __forceinline__ void cp_commit() {
    asm volatile("cp.async.commit_group;");
}
__device__ __forceinline__ void cp_wait0() {
    asm volatile("cp.async.wait_group 0;");
}

// ============================================================
// GEMM: out = A[M,K] @ W[N,K]^T + bias  (fp16 mma, fp32 accum)
// AHALF: A is fp16 in gmem (raw copy); else fp32 (convert on STS)
// MODE 0: fp32 [M,E]; 1: fp16 [b,h,s,d]; 2: fp16 [b,h,d,s]
// ============================================================
template<int MODE, int AHALF>
__global__ __launch_bounds__(256, 2) void gemm_h(
    const void* __restrict__ Av, const float* __restrict__ W,
    const float* __restrict__ bias, void* __restrict__ outv, int K)
{
    __shared__ __align__(16) __half As[2][128 * GST];
    __shared__ __align__(16) __half Ws[2][128 * GST];
    const int tid = threadIdx.x, lane = tid & 31, warp = tid >> 5;
    const int rowBase = blockIdx.y * 128, colBase = blockIdx.x * 128;
    const int lr = tid >> 1, lk = (tid & 1) * 8;

    const float*  Af = (const float*)Av;
    const __half* Ah = (const __half*)Av;
    const float*  Wp = W + (size_t)(colBase + lr) * K + lk;

    float acc[4][4][4];
#pragma unroll
    for (int i = 0; i < 4; i++)
#pragma unroll
        for (int j = 0; j < 4; j++)
#pragma unroll
            for (int l = 0; l < 4; l++) acc[i][j][l] = 0.f;

    const int wm = warp & 1, wn = warp >> 1;
    const uint32_t sA = (uint32_t)__cvta_generic_to_shared(&As[0][0]);
    const uint32_t sW = (uint32_t)__cvta_generic_to_shared(&Ws[0][0]);
    // A-frag: row=(l&7)+((l>>3)&1)*8, col16B=(l>>4)
    const uint32_t aOff = ((wm * 64 + (lane & 7) + ((lane >> 3) & 1) * 8) * GST
                          + (lane >> 4) * 8) * 2;
    // B-frag: row=(l&7)+(l>>4)*8, col16B=(l>>3)&1
    const uint32_t bOff = ((wn * 32 + (lane & 7) + (lane >> 4) * 8) * GST
                          + ((lane >> 3) & 1) * 8) * 2;
    const uint32_t stageB = 128 * GST * 2;

    uint32_t ua[4], uw[4];
    // stage 0 load
    if (AHALF) {
        const uint4 v = *(const uint4*)(Ah + (size_t)(rowBase + lr) * K + lk);
        ua[0] = v.x; ua[1] = v.y; ua[2] = v.z; ua[3] = v.w;
    } else {
        const float4 a0 = *(const float4*)(Af + (size_t)(rowBase + lr) * K + lk);
        const float4 a1 = *(const float4*)(Af + (size_t)(rowBase + lr) * K + lk + 4);
        ua[0] = f2h2(a0.x, a0.y); ua[1] = f2h2(a0.z, a0.w);
        ua[2] = f2h2(a1.x, a1.y); ua[3] = f2h2(a1.z, a1.w);
    }
    {
        const float4 w0 = *(const float4*)Wp;
        const float4 w1 = *(const float4*)(Wp + 4);
        uw[0] = f2h2(w0.x, w0.y); uw[1] = f2h2(w0.z, w0.w);
        uw[2] = f2h2(w1.x, w1.y); uw[3] = f2h2(w1.z, w1.w);
    }
    *(uint4*)&As[0][lr * GST + lk] = *(uint4*)ua;
    *(uint4*)&Ws[0][lr * GST + lk] = *(uint4*)uw;
    __syncthreads();

    for (int kk = 0; kk < K; kk += 16) {
        const int cur = (kk >> 4) & 1;
        const bool more = (kk + 16 < K);
        if (more) {
            if (AHALF) {
                const uint4 v = *(const uint4*)(Ah + (size_t)(rowBase + lr) * K + kk + 16 + lk);
                ua[0] = v.x; ua[1] = v.y; ua[2] = v.z; ua[3] = v.w;
            } else {
                const float4 a0 = *(const float4*)(Af + (size_t)(rowBase + lr) * K + kk + 16 + lk);
                const float4 a1 = *(const float4*)(Af + (size_t)(rowBase + lr) * K + kk + 20 + lk);
                ua[0] = f2h2(a0.x, a0.y); ua[1] = f2h2(a0.z, a0.w);
                ua[2] = f2h2(a1.x, a1.y); ua[3] = f2h2(a1.z, a1.w);
            }
            const float4 w0 = *(const float4*)(Wp + kk + 16);
            const float4 w1 = *(const float4*)(Wp + kk + 20);
            uw[0] = f2h2(w0.x, w0.y); uw[1] = f2h2(w0.z, w0.w);
            uw[2] = f2h2(w1.x, w1.y); uw[3] = f2h2(w1.z, w1.w);
        }
        const uint32_t aAddr = sA + cur * stageB + aOff;
        const uint32_t bAddr = sW + cur * stageB + bOff;
        uint32_t bF[2][4];
#pragma unroll
        for (int np = 0; np < 2; np++) ldsm4(bF[np], bAddr + np * (16 * GST * 2));
#pragma unroll
        for (int mt = 0; mt < 4; mt++) {
            uint32_t aF[4];
            ldsm4(aF, aAddr + mt * (16 * GST * 2));
#pragma unroll
            for (int nt = 0; nt < 4; nt++)
                mma16(acc[mt][nt], aF, bF[nt >> 1][(nt & 1) * 2], bF[nt >> 1][(nt & 1) * 2 + 1]);
        }
        if (more) {
            const int nxt = cur ^ 1;
            *(uint4*)&As[nxt][lr * GST + lk] = *(uint4*)ua;
            *(uint4*)&Ws[nxt][lr * GST + lk] = *(uint4*)uw;
        }
        __syncthreads();
    }

    const int gid = lane >> 2, tig = lane & 3;
#pragma unroll
    for (int nt = 0; nt < 4; nt++) {
        const int col0 = colBase + wn * 32 + nt * 8 + tig * 2;
        const float bb0 = bias[col0], bb1 = bias[col0 + 1];
#pragma unroll
        for (int mt = 0; mt < 4; mt++) {
            const int row0 = rowBase + wm * 64 + mt * 16 + gid;
            const float v00 = acc[mt][nt][0] + bb0, v01 = acc[mt][nt][1] + bb1;
            const float v10 = acc[mt][nt][2] + bb0, v11 = acc[mt][nt][3] + bb1;
            if (MODE == 0) {
                float* out = (float*)outv;
                *(float2*)&out[(size_t)row0 * E + col0]       = make_float2(v00, v01);
                *(float2*)&out[(size_t)(row0 + 8) * E + col0] = make_float2(v10, v11);
            } else if (MODE == 1) {
                __half* out = (__half*)outv;
                const int b = row0 >> 11, s0 = row0 & (S - 1);
                const int h = col0 >> 6, d0 = col0 & 63;
                const size_t base = ((size_t)(b * H + h)) * S;
                *(uint32_t*)&out[(base + s0) * D + d0]     = f2h2(v00, v01);
                *(uint32_t*)&out[(base + s0 + 8) * D + d0] = f2h2(v10, v11);
            } else {
                __half* out = (__half*)outv;
                const int b = row0 >> 11, s0 = row0 & (S - 1);
                const int h = col0 >> 6, d0 = col0 & 63;
                const size_t base = ((size_t)(b * H + h)) * D;
                out[(base + d0) * S + s0]         = __float2half_rn(v00);
                out[(base + d0 + 1) * S + s0]     = __float2half_rn(v01);
                out[(base + d0) * S + s0 + 8]     = __float2half_rn(v10);
                out[(base + d0 + 1) * S + s0 + 8] = __float2half_rn(v11);
            }
        }
    }
}

// ============================================================
// Fused attention (fp16 mma): 128-row stripe, warp-owned rows.
// ============================================================
extern __shared__ char fsm[];

__global__ __launch_bounds__(256, 2) void fused_attn(
    const __half* __restrict__ q, const __half* __restrict__ k,
    const __half* __restrict__ vt, float* __restrict__ attn,
    __half* __restrict__ ctx)
{
    const int bh = blockIdx.x;
    const int it = 15 - blockIdx.y;
    const int nj = 2 * (it + 1);
    const int tid = threadIdx.x, lane = tid & 31, w = tid >> 5;
    const int gid = lane >> 2, tig = lane & 3;

    __half* QP = (__half*)fsm;              // 128*KST (Q staging, then P)
    __half* Ks = QP + 128 * KST;            // 2 x 64*KST
    __half* Vs = Ks + 2 * 64 * KST;         // 2 x 64*KST

    const uint32_t sQP = (uint32_t)__cvta_generic_to_shared(QP);
    const uint32_t sK  = (uint32_t)__cvta_generic_to_shared(Ks);
    const uint32_t sV  = (uint32_t)__cvta_generic_to_shared(Vs);
    const uint32_t bufB = 64 * KST * 2;

    const __half* qbase = q + ((size_t)bh * S + (size_t)it * 128) * D;
    const __half* kbase = k + (size_t)bh * S * D;
    const __half* vbase = vt + (size_t)bh * D * S;

    // A-frag addr (QP): row=(l&7)+((l>>3)&1)*8, col16B=(l>>4)
    const uint32_t aAddr = sQP + ((w * 16 + (lane & 7) + ((lane >> 3) & 1) * 8) * KST
                                  + (lane >> 4) * 8) * 2;
    // B-frag addr (K/V): row=(l&7)+(l>>4)*8, col16B=(l>>3)&1
    const uint32_t bOff = (((lane & 7) + (lane >> 4) * 8) * KST
                           + ((lane >> 3) & 1) * 8) * 2;

    // ---- prologue: stage Q (4 chunks/thr), prefetch K0 (2 chunks/thr) ----
#pragma unroll
    for (int t = 0; t < 4; t++) {
        const int c = tid + t * 256;             // 1024 chunks: 128 rows x 8
        const int r = c >> 3, c8 = (c & 7) * 8;
        cpa16(sQP + (r * KST + c8) * 2, qbase + r * 64 + c8);
    }
    cp_commit();
#pragma unroll
    for (int t = 0; t < 2; t++) {
        const int c = tid + t * 256;             // 512 chunks: 64 rows x 8
        const int r = c >> 3, c8 = (c & 7) * 8;
        cpa16(sK + (r * KST + c8) * 2, kbase + (size_t)r * 64 + c8);
    }
    cp_commit();
    cp_wait0();
    __syncthreads();

    uint32_t aQ[4][4];                           // 4 k16 chunks of D=64
#pragma unroll
    for (int kc = 0; kc < 4; kc++) ldsm4(aQ[kc], aAddr + kc * 32);
    __syncthreads();

    float as[8][4];
    float Zacc[2] = {0.f, 0.f};

    // =================== PASS 1: Z (warp-local) ===================
    for (int jt = 0; jt < nj; jt++) {
        const uint32_t kb = sK + (jt & 1) * bufB + bOff;
        if (jt + 1 < nj) {
#pragma unroll
            for (int t = 0; t < 2; t++) {
                const int c = tid + t * 256;
                const int r = c >> 3, c8 = (c & 7) * 8;
                cpa16(sK + ((jt + 1) & 1) * bufB + (r * KST + c8) * 2,
                      kbase + (size_t)((jt + 1) * 64 + r) * 64 + c8);
            }
            cp_commit();
        }
#pragma unroll
        for (int nt = 0; nt < 8; nt++)
#pragma unroll
            for (int c = 0; c < 4; c++) as[nt][c] = 0.f;
#pragma unroll
        for (int kp = 0; kp < 4; kp++) {
#pragma unroll
            for (int np = 0; np < 4; np++) {
                uint32_t bF[4];
                ldsm4(bF, kb + np * (16 * KST * 2) + kp * 32);
                mma16(as[np * 2],     aQ[kp], bF[0], bF[1]);
                mma16(as[np * 2 + 1], aQ[kp], bF[2], bF[3]);
            }
        }
        const bool diag = (jt >= 2 * it);
#pragma unroll
        for (int h = 0; h < 2; h++) {
            const int li = it * 128 + w * 16 + gid + h * 8;
            float z = 0.f;
#pragma unroll
            for (int nt = 0; nt < 8; nt++) {
                const int lj = jt * 64 + nt * 8 + tig * 2;
                float e0 = __expf(as[nt][h * 2]     * 0.125f);
                float e1 = __expf(as[nt][h * 2 + 1] * 0.125f);
                if (diag) { if (lj > li) e0 = 0.f; if (lj + 1 > li) e1 = 0.f; }
                z += e0 + e1;
            }
            Zacc[h] += z;
        }
        if (jt + 1 < nj) { cp_wait0(); __syncthreads(); }
    }

    float Zi[2];
#pragma unroll
    for (int h = 0; h < 2; h++) {
        float z = Zacc[h];
        z += __shfl_xor_sync(0xffffffffu, z, 1);
        z += __shfl_xor_sync(0xffffffffu, z, 2);
        Zi[h] = 1.f / z;
    }

    // =================== PASS 2: p + P@V ===================
    __syncthreads();
#pragma unroll
    for (int t = 0; t < 2; t++) {
        const int c = tid + t * 256;
        const int r = c >> 3, c8 = (c & 7) * 8;
        cpa16(sK + (r * KST + c8) * 2, kbase + (size_t)r * 64 + c8);
        cpa16(sV + (r * KST + c8) * 2, vbase + (size_t)r * S + c8);
    }
    cp_commit();
    cp_wait0();
    __syncthreads();

    float cacc[8][4];
#pragma unroll
    for (int nt = 0; nt < 8; nt++)
#pragma unroll
        for (int c = 0; c < 4; c++) cacc[nt][c] = 0.f;

    for (int jt = 0; jt < nj; jt++) {
        const uint32_t kb = sK + (jt & 1) * bufB + bOff;
        const uint32_t vb = sV + (jt & 1) * bufB + bOff;
        if (jt + 1 < nj) {
#pragma unroll
            for (int t = 0; t < 2; t++) {
                const int c = tid + t * 256;
                const int r = c >> 3, c8 = (c & 7) * 8;
                cpa16(sK + ((jt + 1) & 1) * bufB + (r * KST + c8) * 2,
                      kbase + (size_t)((jt + 1) * 64 + r) * 64 + c8);
                cpa16(sV + ((jt + 1) & 1) * bufB + (r * KST + c8) * 2,
                      vbase + (size_t)r * S + (jt + 1) * 64 + c8);
            }
            cp_commit();
        }
#pragma unroll
        for (int nt = 0; nt < 8; nt++)
#pragma unroll
            for (int c = 0; c < 4; c++) as[nt][c] = 0.f;
#pragma unroll
        for (int kp = 0; kp < 4; kp++) {
#pragma unroll
            for (int np = 0; np < 4; np++) {
                uint32_t bF[4];
                ldsm4(bF, kb + np * (16 * KST * 2) + kp * 32);
                mma16(as[np * 2],     aQ[kp], bF[0], bF[1]);
                mma16(as[np * 2 + 1], aQ[kp], bF[2], bF[3]);
            }
        }
        // p = exp(s)/Z ; STG fp32 to attn ; STS fp16 to warp-private P slice
        const bool diag = (jt >= 2 * it);
#pragma unroll
        for (int h = 0; h < 2; h++) {
            const int rl = w * 16 + gid + h * 8;
            const int gi = it * 128 + rl;
            float* prow = attn + ((size_t)bh * S + gi) * S + jt * 64;
            __half* psrow = QP + rl * KST;
#pragma unroll
            for (int nt = 0; nt < 8; nt++) {
                const int lj = jt * 64 + nt * 8 + tig * 2;
                float p0 = __expf(as[nt][h * 2]     * 0.125f) * Zi[h];
                float p1 = __expf(as[nt][h * 2 + 1] * 0.125f) * Zi[h];
                if (diag) { if (lj > gi) p0 = 0.f; if (lj + 1 > gi) p1 = 0.f; }
                *(float2*)(prow + nt * 8 + tig * 2) = make_float2(p0, p1);
                *(uint32_t*)(psrow + nt * 8 + tig * 2) = f2h2(p0, p1);
            }
        }
        __syncwarp();

        // ctx += P(16x64) @ V(64x64)  (B = V^T tile [d][j])
#pragma unroll
        for (int kp = 0; kp < 4; kp++) {
            uint32_t aP[4];
            ldsm4(aP, aAddr + kp * 32);
#pragma unroll
            for (int np = 0; np < 4; np++) {
                uint32_t bF[4];
                ldsm4(bF, vb + np * (16 * KST * 2) + kp * 32);
                mma16(cacc[np * 2],     aP, bF[0], bF[1]);
                mma16(cacc[np * 2 + 1], aP, bF[2], bF[3]);
            }
        }
        if (jt + 1 < nj) { cp_wait0(); __syncthreads(); }
    }

    // ctx epilogue: fp16 [b,s,h,d] == [M,E]
    const int b = bh >> 4, hh = bh & 15;
    const int s0 = it * 128 + w * 16 + gid;
#pragma unroll
    for (int nt = 0; nt < 8; nt++) {
        const int d0 = nt * 8 + tig * 2;
        *(uint32_t*)&ctx[((size_t)(b * S + s0)) * E + hh * D + d0] =
            f2h2(cacc[nt][0], cacc[nt][1]);
        *(uint32_t*)&ctx[((size_t)(b * S + s0 + 8)) * E + hh * D + d0] =
            f2h2(cacc[nt][2], cacc[nt][3]);
    }

    // zero-fill columns beyond the causal edge
    const int zc0 = nj * 64;
    if (zc0 < S) {
        const int r = tid >> 1;
        float* row = attn + ((size_t)bh * S + it * 128 + r) * S;
        const float4 z = make_float4(0.f, 0.f, 0.f, 0.f);
        for (int c = zc0 + (tid & 1) * 4; c < S; c += 8)
            *(float4*)(row + c) = z;
    }
}

// ============================================================
// launch
// ============================================================
extern "C" void kernel_launch(void* const* d_in, const int* in_sizes, int n_in,
                              void* d_out_v, int out_size)
{
    const float* query = (const float*)d_in[0];
    const float* key_  = (const float*)d_in[1];
    const float* value = (const float*)d_in[2];
    const float* Wq = (const float*)d_in[4];
    const float* bq = (const float*)d_in[5];
    const float* Wk = (const float*)d_in[6];
    const float* bk = (const float*)d_in[7];
    const float* Wv = (const float*)d_in[8];
    const float* bv = (const float*)d_in[9];
    const float* Wo = (const float*)d_in[10];
    const float* bo = (const float*)d_in[11];
    float* d_out = (float*)d_out_v;

    __half *qp, *kp, *vtp, *cp;
    float *op, *ap;
    cudaGetSymbolAddress((void**)&qp,  g_q);
    cudaGetSymbolAddress((void**)&kp,  g_k);
    cudaGetSymbolAddress((void**)&vtp, g_vt);
    cudaGetSymbolAddress((void**)&cp,  g_ctx);
    cudaGetSymbolAddress((void**)&op,  g_out);
    cudaGetSymbolAddress((void**)&ap,  g_attn);

    float* out_ptr;
    float* attn_ptr;
    long long osz = (long long)out_size;
    if (osz >= (long long)OUT_N + (long long)ATT_N) {
        out_ptr = d_out; attn_ptr = d_out + OUT_N;
    } else if (osz == (long long)OUT_N) {
        out_ptr = d_out; attn_ptr = ap;
    } else {
        attn_ptr = d_out; out_ptr = op;
    }

    const int FUSED_SMEM = (128 * KST + 4 * 64 * KST) * 2;   // 55296 B
    cudaFuncSetAttribute(fused_attn, cudaFuncAttributeMaxDynamicSharedMemorySize,
                         FUSED_SMEM);

    dim3 gP(E / 128, M_ROWS / 128);
    gemm_h<1, 0><<<gP, 256>>>(query, Wq, bq, qp,  E);
    gemm_h<1, 0><<<gP, 256>>>(key_,  Wk, bk, kp,  E);
    gemm_h<2, 0><<<gP, 256>>>(value, Wv, bv, vtp, E);

    dim3 gF(Bn * H, 16);
    fused_attn<<<gF, 256, FUSED_SMEM>>>(qp, kp, vtp, attn_ptr, cp);

    gemm_h<0, 1><<<gP, 256>>>(cp, Wo, bo, out_ptr, E);
}

// round 10
// speedup vs baseline: 5.1509x; 1.0707x over previous
#include <cuda_runtime.h>
#include <cuda_fp16.h>
#include <cstdint>

// ---------------- problem constants ----------------
#define S   2048
#define E   1024
#define H   16
#define D   64
#define Bn  2
#define M_ROWS (Bn * S)
#define OUT_N  (Bn * S * E)
#define ATT_N  (134217728)
#define GST 40      // gemm smem row stride (halves), BK=32 + pad
#define KST 72      // fused smem row stride (halves)

// ---------------- device scratch ----------------
__device__ __half g_q[Bn * H * S * D];
__device__ __half g_k[Bn * H * S * D];
__device__ __half g_vt[Bn * H * D * S];   // V transposed: [b,h,d,s]
__device__ __half g_ctx[Bn * S * E];
__device__ float  g_out[OUT_N];
__device__ float  g_attn[ATT_N];

// ---------------- helpers ----------------
__device__ __forceinline__ uint32_t f2h2(float a, float b) {
    __half2 h = __floats2half2_rn(a, b);
    return *(uint32_t*)&h;
}
__device__ __forceinline__ void ldsm4(uint32_t r[4], uint32_t addr) {
    asm volatile("ldmatrix.sync.aligned.m8n8.x4.shared.b16 {%0,%1,%2,%3}, [%4];"
        : "=r"(r[0]), "=r"(r[1]), "=r"(r[2]), "=r"(r[3]) : "r"(addr));
}
__device__ __forceinline__ void mma16(float c[4], const uint32_t a[4],
                                      uint32_t b0, uint32_t b1) {
    asm volatile("mma.sync.aligned.m16n8k16.row.col.f32.f16.f16.f32 "
        "{%0,%1,%2,%3},{%4,%5,%6,%7},{%8,%9},{%0,%1,%2,%3};"
        : "+f"(c[0]), "+f"(c[1]), "+f"(c[2]), "+f"(c[3])
        : "r"(a[0]), "r"(a[1]), "r"(a[2]), "r"(a[3]), "r"(b0), "r"(b1));
}
__device__ __forceinline__ void cpa16(uint32_t dst, const void* src) {
    asm volatile("cp.async.ca.shared.global [%0], [%1], 16;" :: "r"(dst), "l"(src));
}
__device__ __forceinline__ void cp_commit() {
    asm volatile("cp.async.commit_group;");
}
__device__ __forceinline__ void cp_wait0() {
    asm volatile("cp.async.wait_group 0;");
}

// ============================================================
// GEMM: out = A[M,K] @ W[N,K]^T + bias  (fp16 mma, BK=32)
// grid (8, 32, nz): z selects {A, W, bias, out, mode}.
// mode 0: fp32 [M,E]; 1: fp16 [b,h,s,d]; 2: fp16 [b,h,d,s]
// AHALF: A is fp16 in gmem
// ============================================================
template<int AHALF>
__global__ __launch_bounds__(256, 2) void gemm_h(
    const void* A0, const void* A1, const void* A2,
    const float* W0, const float* W1, const float* W2,
    const float* b0p, const float* b1p, const float* b2p,
    void* o0, void* o1, void* o2,
    int m0, int m1, int m2, int K)
{
    const int z = blockIdx.z;
    const void*  Av   = (z == 0) ? A0 : (z == 1) ? A1 : A2;
    const float* W    = (z == 0) ? W0 : (z == 1) ? W1 : W2;
    const float* bias = (z == 0) ? b0p : (z == 1) ? b1p : b2p;
    void*        outv = (z == 0) ? o0 : (z == 1) ? o1 : o2;
    const int    mode = (z == 0) ? m0 : (z == 1) ? m1 : m2;

    __shared__ __align__(16) __half As[2][128 * GST];
    __shared__ __align__(16) __half Ws[2][128 * GST];
    const int tid = threadIdx.x, lane = tid & 31, warp = tid >> 5;
    const int rowBase = blockIdx.y * 128, colBase = blockIdx.x * 128;
    const int lr = tid >> 1, hc = (tid & 1) * 16;

    const float*  Af = (const float*)Av;
    const __half* Ah = (const __half*)Av;
    const float*  Wp = W + (size_t)(colBase + lr) * K + hc;

    float acc[4][4][4];
#pragma unroll
    for (int i = 0; i < 4; i++)
#pragma unroll
        for (int j = 0; j < 4; j++)
#pragma unroll
            for (int l = 0; l < 4; l++) acc[i][j][l] = 0.f;

    const int wm = warp & 1, wn = warp >> 1;
    const uint32_t sA = (uint32_t)__cvta_generic_to_shared(&As[0][0]);
    const uint32_t sW = (uint32_t)__cvta_generic_to_shared(&Ws[0][0]);
    const uint32_t aOff = ((wm * 64 + (lane & 7) + ((lane >> 3) & 1) * 8) * GST
                          + (lane >> 4) * 8) * 2;
    const uint32_t bOff = ((wn * 32 + (lane & 7) + (lane >> 4) * 8) * GST
                          + ((lane >> 3) & 1) * 8) * 2;
    const uint32_t stageB = 128 * GST * 2;

    uint32_t ua[8], uw[8];
    auto loadA = [&](int k0) {
        if (AHALF) {
            const uint4 v0 = *(const uint4*)(Ah + (size_t)(rowBase + lr) * K + k0 + hc);
            const uint4 v1 = *(const uint4*)(Ah + (size_t)(rowBase + lr) * K + k0 + hc + 8);
            ua[0] = v0.x; ua[1] = v0.y; ua[2] = v0.z; ua[3] = v0.w;
            ua[4] = v1.x; ua[5] = v1.y; ua[6] = v1.z; ua[7] = v1.w;
        } else {
            const float* p = Af + (size_t)(rowBase + lr) * K + k0 + hc;
            const float4 a0 = *(const float4*)p,        a1 = *(const float4*)(p + 4);
            const float4 a2 = *(const float4*)(p + 8),  a3 = *(const float4*)(p + 12);
            ua[0] = f2h2(a0.x, a0.y); ua[1] = f2h2(a0.z, a0.w);
            ua[2] = f2h2(a1.x, a1.y); ua[3] = f2h2(a1.z, a1.w);
            ua[4] = f2h2(a2.x, a2.y); ua[5] = f2h2(a2.z, a2.w);
            ua[6] = f2h2(a3.x, a3.y); ua[7] = f2h2(a3.z, a3.w);
        }
        const float4 w0 = *(const float4*)(Wp + k0),      w1 = *(const float4*)(Wp + k0 + 4);
        const float4 w2 = *(const float4*)(Wp + k0 + 8),  w3 = *(const float4*)(Wp + k0 + 12);
        uw[0] = f2h2(w0.x, w0.y); uw[1] = f2h2(w0.z, w0.w);
        uw[2] = f2h2(w1.x, w1.y); uw[3] = f2h2(w1.z, w1.w);
        uw[4] = f2h2(w2.x, w2.y); uw[5] = f2h2(w2.z, w2.w);
        uw[6] = f2h2(w3.x, w3.y); uw[7] = f2h2(w3.z, w3.w);
    };
    auto stsStage = [&](int buf) {
        *(uint4*)&As[buf][lr * GST + hc]     = *(uint4*)&ua[0];
        *(uint4*)&As[buf][lr * GST + hc + 8] = *(uint4*)&ua[4];
        *(uint4*)&Ws[buf][lr * GST + hc]     = *(uint4*)&uw[0];
        *(uint4*)&Ws[buf][lr * GST + hc + 8] = *(uint4*)&uw[4];
    };

    loadA(0);
    stsStage(0);
    __syncthreads();

    for (int k0 = 0; k0 < K; k0 += 32) {
        const int cur = (k0 >> 5) & 1;
        const bool more = (k0 + 32 < K);
        if (more) loadA(k0 + 32);
#pragma unroll
        for (int ks = 0; ks < 2; ks++) {
            uint32_t bF[2][4];
#pragma unroll
            for (int np = 0; np < 2; np++)
                ldsm4(bF[np], sW + cur * stageB + bOff + np * (16 * GST * 2) + ks * 32);
#pragma unroll
            for (int mt = 0; mt < 4; mt++) {
                uint32_t aF[4];
                ldsm4(aF, sA + cur * stageB + aOff + mt * (16 * GST * 2) + ks * 32);
#pragma unroll
                for (int nt = 0; nt < 4; nt++)
                    mma16(acc[mt][nt], aF, bF[nt >> 1][(nt & 1) * 2], bF[nt >> 1][(nt & 1) * 2 + 1]);
            }
        }
        if (more) stsStage(cur ^ 1);
        __syncthreads();
    }

    const int gid = lane >> 2, tig = lane & 3;
#pragma unroll
    for (int nt = 0; nt < 4; nt++) {
        const int col0 = colBase + wn * 32 + nt * 8 + tig * 2;
        const float bb0 = bias[col0], bb1 = bias[col0 + 1];
#pragma unroll
        for (int mt = 0; mt < 4; mt++) {
            const int row0 = rowBase + wm * 64 + mt * 16 + gid;
            const float v00 = acc[mt][nt][0] + bb0, v01 = acc[mt][nt][1] + bb1;
            const float v10 = acc[mt][nt][2] + bb0, v11 = acc[mt][nt][3] + bb1;
            if (mode == 0) {
                float* out = (float*)outv;
                *(float2*)&out[(size_t)row0 * E + col0]       = make_float2(v00, v01);
                *(float2*)&out[(size_t)(row0 + 8) * E + col0] = make_float2(v10, v11);
            } else if (mode == 1) {
                __half* out = (__half*)outv;
                const int b = row0 >> 11, s0 = row0 & (S - 1);
                const int h = col0 >> 6, d0 = col0 & 63;
                const size_t base = ((size_t)(b * H + h)) * S;
                *(uint32_t*)&out[(base + s0) * D + d0]     = f2h2(v00, v01);
                *(uint32_t*)&out[(base + s0 + 8) * D + d0] = f2h2(v10, v11);
            } else {
                __half* out = (__half*)outv;
                const int b = row0 >> 11, s0 = row0 & (S - 1);
                const int h = col0 >> 6, d0 = col0 & 63;
                const size_t base = ((size_t)(b * H + h)) * D;
                out[(base + d0) * S + s0]         = __float2half_rn(v00);
                out[(base + d0 + 1) * S + s0]     = __float2half_rn(v01);
                out[(base + d0) * S + s0 + 8]     = __float2half_rn(v10);
                out[(base + d0 + 1) * S + s0 + 8] = __float2half_rn(v11);
            }
        }
    }
}

// ============================================================
// Fused attention (fp16): register P->A fragments, no P smem.
// ============================================================
extern __shared__ char fsm[];

__global__ __launch_bounds__(256, 2) void fused_attn(
    const __half* __restrict__ q, const __half* __restrict__ k,
    const __half* __restrict__ vt, float* __restrict__ attn,
    __half* __restrict__ ctx)
{
    const int bh = blockIdx.x;
    const int it = 15 - blockIdx.y;
    const int nj = 2 * (it + 1);
    const int tid = threadIdx.x, lane = tid & 31, w = tid >> 5;
    const int gid = lane >> 2, tig = lane & 3;

    __half* QP = (__half*)fsm;              // 128*KST (Q staging)
    __half* Ks = QP + 128 * KST;            // 2 x 64*KST
    __half* Vs = Ks + 2 * 64 * KST;         // 2 x 64*KST

    const uint32_t sQP = (uint32_t)__cvta_generic_to_shared(QP);
    const uint32_t sK  = (uint32_t)__cvta_generic_to_shared(Ks);
    const uint32_t sV  = (uint32_t)__cvta_generic_to_shared(Vs);
    const uint32_t bufB = 64 * KST * 2;

    const __half* qbase = q + ((size_t)bh * S + (size_t)it * 128) * D;
    const __half* kbase = k + (size_t)bh * S * D;
    const __half* vbase = vt + (size_t)bh * D * S;

    const uint32_t aAddr = sQP + ((w * 16 + (lane & 7) + ((lane >> 3) & 1) * 8) * KST
                                  + (lane >> 4) * 8) * 2;
    const uint32_t bOff = (((lane & 7) + (lane >> 4) * 8) * KST
                           + ((lane >> 3) & 1) * 8) * 2;

    // ---- prologue: stage Q, prefetch K0 ----
#pragma unroll
    for (int t = 0; t < 4; t++) {
        const int c = tid + t * 256;
        const int r = c >> 3, c8 = (c & 7) * 8;
        cpa16(sQP + (r * KST + c8) * 2, qbase + r * 64 + c8);
    }
    cp_commit();
#pragma unroll
    for (int t = 0; t < 2; t++) {
        const int c = tid + t * 256;
        const int r = c >> 3, c8 = (c & 7) * 8;
        cpa16(sK + (r * KST + c8) * 2, kbase + (size_t)r * 64 + c8);
    }
    cp_commit();
    cp_wait0();
    __syncthreads();

    uint32_t aQ[4][4];
#pragma unroll
    for (int kc = 0; kc < 4; kc++) ldsm4(aQ[kc], aAddr + kc * 32);
    __syncthreads();

    float as[8][4];
    float Zacc[2] = {0.f, 0.f};

    // =================== PASS 1: Z (warp-local) ===================
    for (int jt = 0; jt < nj; jt++) {
        const uint32_t kb = sK + (jt & 1) * bufB + bOff;
        if (jt + 1 < nj) {
#pragma unroll
            for (int t = 0; t < 2; t++) {
                const int c = tid + t * 256;
                const int r = c >> 3, c8 = (c & 7) * 8;
                cpa16(sK + ((jt + 1) & 1) * bufB + (r * KST + c8) * 2,
                      kbase + (size_t)((jt + 1) * 64 + r) * 64 + c8);
            }
            cp_commit();
        }
#pragma unroll
        for (int nt = 0; nt < 8; nt++)
#pragma unroll
            for (int c = 0; c < 4; c++) as[nt][c] = 0.f;
#pragma unroll
        for (int kp = 0; kp < 4; kp++) {
#pragma unroll
            for (int np = 0; np < 4; np++) {
                uint32_t bF[4];
                ldsm4(bF, kb + np * (16 * KST * 2) + kp * 32);
                mma16(as[np * 2],     aQ[kp], bF[0], bF[1]);
                mma16(as[np * 2 + 1], aQ[kp], bF[2], bF[3]);
            }
        }
        const bool diag = (jt >= 2 * it);
#pragma unroll
        for (int h = 0; h < 2; h++) {
            const int li = it * 128 + w * 16 + gid + h * 8;
            float z = 0.f;
#pragma unroll
            for (int nt = 0; nt < 8; nt++) {
                const int lj = jt * 64 + nt * 8 + tig * 2;
                float e0 = __expf(as[nt][h * 2]     * 0.125f);
                float e1 = __expf(as[nt][h * 2 + 1] * 0.125f);
                if (diag) { if (lj > li) e0 = 0.f; if (lj + 1 > li) e1 = 0.f; }
                z += e0 + e1;
            }
            Zacc[h] += z;
        }
        if (jt + 1 < nj) { cp_wait0(); __syncthreads(); }
    }

    float Zi[2];
#pragma unroll
    for (int h = 0; h < 2; h++) {
        float z = Zacc[h];
        z += __shfl_xor_sync(0xffffffffu, z, 1);
        z += __shfl_xor_sync(0xffffffffu, z, 2);
        Zi[h] = 1.f / z;
    }

    // =================== PASS 2: p + P@V (register P) ===================
    __syncthreads();
#pragma unroll
    for (int t = 0; t < 2; t++) {
        const int c = tid + t * 256;
        const int r = c >> 3, c8 = (c & 7) * 8;
        cpa16(sK + (r * KST + c8) * 2, kbase + (size_t)r * 64 + c8);
        cpa16(sV + (r * KST + c8) * 2, vbase + (size_t)r * S + c8);
    }
    cp_commit();
    cp_wait0();
    __syncthreads();

    float cacc[8][4];
#pragma unroll
    for (int nt = 0; nt < 8; nt++)
#pragma unroll
        for (int c = 0; c < 4; c++) cacc[nt][c] = 0.f;

    const int gi0 = it * 128 + w * 16 + gid;

    for (int jt = 0; jt < nj; jt++) {
        const uint32_t kb = sK + (jt & 1) * bufB + bOff;
        const uint32_t vb = sV + (jt & 1) * bufB + bOff;
        if (jt + 1 < nj) {
#pragma unroll
            for (int t = 0; t < 2; t++) {
                const int c = tid + t * 256;
                const int r = c >> 3, c8 = (c & 7) * 8;
                cpa16(sK + ((jt + 1) & 1) * bufB + (r * KST + c8) * 2,
                      kbase + (size_t)((jt + 1) * 64 + r) * 64 + c8);
                cpa16(sV + ((jt + 1) & 1) * bufB + (r * KST + c8) * 2,
                      vbase + (size_t)r * S + (jt + 1) * 64 + c8);
            }
            cp_commit();
        }
#pragma unroll
        for (int nt = 0; nt < 8; nt++)
#pragma unroll
            for (int c = 0; c < 4; c++) as[nt][c] = 0.f;
#pragma unroll
        for (int kp = 0; kp < 4; kp++) {
#pragma unroll
            for (int np = 0; np < 4; np++) {
                uint32_t bF[4];
                ldsm4(bF, kb + np * (16 * KST * 2) + kp * 32);
                mma16(as[np * 2],     aQ[kp], bF[0], bF[1]);
                mma16(as[np * 2 + 1], aQ[kp], bF[2], bF[3]);
            }
        }
        // p = exp(s)/Z : write fp32 attn + pack fp16 A-fragments in regs
        const bool diag = (jt >= 2 * it);
        uint32_t pk[8][2];
        float* prow0 = attn + ((size_t)bh * S + gi0) * S + jt * 64;
        float* prow1 = prow0 + (size_t)8 * S;
#pragma unroll
        for (int nt = 0; nt < 8; nt++) {
            const int lj = jt * 64 + nt * 8 + tig * 2;
            float p0 = __expf(as[nt][0] * 0.125f) * Zi[0];
            float p1 = __expf(as[nt][1] * 0.125f) * Zi[0];
            float p2 = __expf(as[nt][2] * 0.125f) * Zi[1];
            float p3 = __expf(as[nt][3] * 0.125f) * Zi[1];
            if (diag) {
                if (lj > gi0)         p0 = 0.f;
                if (lj + 1 > gi0)     p1 = 0.f;
                if (lj > gi0 + 8)     p2 = 0.f;
                if (lj + 1 > gi0 + 8) p3 = 0.f;
            }
            *(float2*)(prow0 + nt * 8 + tig * 2) = make_float2(p0, p1);
            *(float2*)(prow1 + nt * 8 + tig * 2) = make_float2(p2, p3);
            pk[nt][0] = f2h2(p0, p1);
            pk[nt][1] = f2h2(p2, p3);
        }

        // ctx += P(16x64) @ V(64x64), P straight from registers
#pragma unroll
        for (int kp = 0; kp < 4; kp++) {
            const uint32_t aP[4] = { pk[2 * kp][0], pk[2 * kp][1],
                                     pk[2 * kp + 1][0], pk[2 * kp + 1][1] };
#pragma unroll
            for (int np = 0; np < 4; np++) {
                uint32_t bF[4];
                ldsm4(bF, vb + np * (16 * KST * 2) + kp * 32);
                mma16(cacc[np * 2],     aP, bF[0], bF[1]);
                mma16(cacc[np * 2 + 1], aP, bF[2], bF[3]);
            }
        }
        if (jt + 1 < nj) { cp_wait0(); __syncthreads(); }
    }

    // ctx epilogue: fp16 [b,s,h,d] == [M,E]
    const int b = bh >> 4, hh = bh & 15;
#pragma unroll
    for (int nt = 0; nt < 8; nt++) {
        const int d0 = nt * 8 + tig * 2;
        *(uint32_t*)&ctx[((size_t)(b * S + gi0)) * E + hh * D + d0] =
            f2h2(cacc[nt][0], cacc[nt][1]);
        *(uint32_t*)&ctx[((size_t)(b * S + gi0 + 8)) * E + hh * D + d0] =
            f2h2(cacc[nt][2], cacc[nt][3]);
    }

    // zero-fill columns beyond the causal edge
    const int zc0 = nj * 64;
    if (zc0 < S) {
        const int r = tid >> 1;
        float* row = attn + ((size_t)bh * S + it * 128 + r) * S;
        const float4 z = make_float4(0.f, 0.f, 0.f, 0.f);
        for (int c = zc0 + (tid & 1) * 4; c < S; c += 8)
            *(float4*)(row + c) = z;
    }
}

// ============================================================
// launch
// ============================================================
extern "C" void kernel_launch(void* const* d_in, const int* in_sizes, int n_in,
                              void* d_out_v, int out_size)
{
    const float* query = (const float*)d_in[0];
    const float* key_  = (const float*)d_in[1];
    const float* value = (const float*)d_in[2];
    const float* Wq = (const float*)d_in[4];
    const float* bq = (const float*)d_in[5];
    const float* Wk = (const float*)d_in[6];
    const float* bk = (const float*)d_in[7];
    const float* Wv = (const float*)d_in[8];
    const float* bv = (const float*)d_in[9];
    const float* Wo = (const float*)d_in[10];
    const float* bo = (const float*)d_in[11];
    float* d_out = (float*)d_out_v;

    __half *qp, *kp, *vtp, *cp;
    float *op, *ap;
    cudaGetSymbolAddress((void**)&qp,  g_q);
    cudaGetSymbolAddress((void**)&kp,  g_k);
    cudaGetSymbolAddress((void**)&vtp, g_vt);
    cudaGetSymbolAddress((void**)&cp,  g_ctx);
    cudaGetSymbolAddress((void**)&op,  g_out);
    cudaGetSymbolAddress((void**)&ap,  g_attn);

    float* out_ptr;
    float* attn_ptr;
    long long osz = (long long)out_size;
    if (osz >= (long long)OUT_N + (long long)ATT_N) {
        out_ptr = d_out; attn_ptr = d_out + OUT_N;
    } else if (osz == (long long)OUT_N) {
        out_ptr = d_out; attn_ptr = ap;
    } else {
        attn_ptr = d_out; out_ptr = op;
    }

    const int FUSED_SMEM = (128 * KST + 4 * 64 * KST) * 2;   // 55296 B
    cudaFuncSetAttribute(fused_attn, cudaFuncAttributeMaxDynamicSharedMemorySize,
                         FUSED_SMEM);

    // merged Q/K/V projections: one launch, z = 0/1/2
    gemm_h<0><<<dim3(E / 128, M_ROWS / 128, 3), 256>>>(
        query, key_, value, Wq, Wk, Wv, bq, bk, bv,
        qp, kp, vtp, 1, 1, 2, E);

    dim3 gF(Bn * H, 16);
    fused_attn<<<gF, 256, FUSED_SMEM>>>(qp, kp, vtp, attn_ptr, cp);

    // output projection (A = fp16 ctx)
    gemm_h<1><<<dim3(E / 128, M_ROWS / 128, 1), 256>>>(
        cp, cp, cp, Wo, Wo, Wo, bo, bo, bo,
        out_ptr, out_ptr, out_ptr, 0, 0, 0, E);
}

// round 11
// speedup vs baseline: 6.5303x; 1.2678x over previous
#include <cuda_runtime.h>
#include <cuda_fp16.h>
#include <cstdint>

// ---------------- problem constants ----------------
#define S   2048
#define E   1024
#define H   16
#define D   64
#define Bn  2
#define M_ROWS (Bn * S)
#define OUT_N  (Bn * S * E)
#define ATT_N  (134217728)
#define GST 40      // gemm smem row stride (halves), BK=32 + pad
#define KST 72      // fused smem row stride (halves)

// ---------------- device scratch ----------------
__device__ __half g_ah[3u * M_ROWS * E];   // fp16 copies of query,key,value
__device__ __half g_wh[4u * E * E];        // fp16 copies of Wq,Wk,Wv,Wo
__device__ __half g_q[Bn * H * S * D];
__device__ __half g_k[Bn * H * S * D];
__device__ __half g_vt[Bn * H * D * S];    // V transposed: [b,h,d,s]
__device__ __half g_ctx[Bn * S * E];
__device__ float  g_out[OUT_N];
__device__ float  g_attn[ATT_N];

// ---------------- helpers ----------------
__device__ __forceinline__ uint32_t f2h2(float a, float b) {
    __half2 h = __floats2half2_rn(a, b);
    return *(uint32_t*)&h;
}
__device__ __forceinline__ void ldsm4(uint32_t r[4], uint32_t addr) {
    asm volatile("ldmatrix.sync.aligned.m8n8.x4.shared.b16 {%0,%1,%2,%3}, [%4];"
        : "=r"(r[0]), "=r"(r[1]), "=r"(r[2]), "=r"(r[3]) : "r"(addr));
}
__device__ __forceinline__ void mma16(float c[4], const uint32_t a[4],
                                      uint32_t b0, uint32_t b1) {
    asm volatile("mma.sync.aligned.m16n8k16.row.col.f32.f16.f16.f32 "
        "{%0,%1,%2,%3},{%4,%5,%6,%7},{%8,%9},{%0,%1,%2,%3};"
        : "+f"(c[0]), "+f"(c[1]), "+f"(c[2]), "+f"(c[3])
        : "r"(a[0]), "r"(a[1]), "r"(a[2]), "r"(a[3]), "r"(b0), "r"(b1));
}
__device__ __forceinline__ void cpa16(uint32_t dst, const void* src) {
    asm volatile("cp.async.ca.shared.global [%0], [%1], 16;" :: "r"(dst), "l"(src));
}
__device__ __forceinline__ void cp_commit() {
    asm volatile("cp.async.commit_group;");
}
__device__ __forceinline__ void cp_wait0() {
    asm volatile("cp.async.wait_group 0;");
}

// ============================================================
// fp32 -> fp16 conversion, z selects tensor (8 elems/thread)
// ============================================================
struct CvtArgs {
    const float* src[7];
    __half*      dst[7];
    int          n[7];
};
__global__ __launch_bounds__(256) void cvt_f2h(CvtArgs a)
{
    const int z = blockIdx.z;
    const int i = (blockIdx.x * 256 + threadIdx.x) * 8;
    if (i >= a.n[z]) return;
    const float4 f0 = *(const float4*)(a.src[z] + i);
    const float4 f1 = *(const float4*)(a.src[z] + i + 4);
    uint4 u;
    u.x = f2h2(f0.x, f0.y); u.y = f2h2(f0.z, f0.w);
    u.z = f2h2(f1.x, f1.y); u.w = f2h2(f1.z, f1.w);
    *(uint4*)(a.dst[z] + i) = u;
}

// ============================================================
// GEMM: out = A[M,K] @ W[N,K]^T + bias  (pure fp16, cp.async)
// grid (8, 32, nz): z selects {A, W, bias, out, mode}.
// mode 0: fp32 [M,E]; 1: fp16 [b,h,s,d]; 2: fp16 [b,h,d,s]
// ============================================================
__global__ __launch_bounds__(256, 2) void gemm_h(
    const __half* A0, const __half* A1, const __half* A2,
    const __half* W0, const __half* W1, const __half* W2,
    const float* b0p, const float* b1p, const float* b2p,
    void* o0, void* o1, void* o2,
    int m0, int m1, int m2, int K)
{
    const int z = blockIdx.z;
    const __half* A    = (z == 0) ? A0 : (z == 1) ? A1 : A2;
    const __half* W    = (z == 0) ? W0 : (z == 1) ? W1 : W2;
    const float*  bias = (z == 0) ? b0p : (z == 1) ? b1p : b2p;
    void*         outv = (z == 0) ? o0 : (z == 1) ? o1 : o2;
    const int     mode = (z == 0) ? m0 : (z == 1) ? m1 : m2;

    __shared__ __align__(16) __half As[2][128 * GST];
    __shared__ __align__(16) __half Ws[2][128 * GST];
    const int tid = threadIdx.x, lane = tid & 31, warp = tid >> 5;
    const int rowBase = blockIdx.y * 128, colBase = blockIdx.x * 128;

    float acc[4][4][4];
#pragma unroll
    for (int i = 0; i < 4; i++)
#pragma unroll
        for (int j = 0; j < 4; j++)
#pragma unroll
            for (int l = 0; l < 4; l++) acc[i][j][l] = 0.f;

    const int wm = warp & 1, wn = warp >> 1;
    const uint32_t sA = (uint32_t)__cvta_generic_to_shared(&As[0][0]);
    const uint32_t sW = (uint32_t)__cvta_generic_to_shared(&Ws[0][0]);
    const uint32_t aOff = ((wm * 64 + (lane & 7) + ((lane >> 3) & 1) * 8) * GST
                          + (lane >> 4) * 8) * 2;
    const uint32_t bOff = ((wn * 32 + (lane & 7) + (lane >> 4) * 8) * GST
                          + ((lane >> 3) & 1) * 8) * 2;
    const uint32_t stageB = 128 * GST * 2;

    // stage copy: 512 x 16B chunks each for A and W; 2 chunks/thread each
    auto stage_cp = [&](int buf, int k0) {
#pragma unroll
        for (int t = 0; t < 2; t++) {
            const int c = tid + t * 256;
            const int r = c >> 2, h8 = (c & 3) * 8;
            cpa16(sA + buf * stageB + (r * GST + h8) * 2,
                  A + (size_t)(rowBase + r) * K + k0 + h8);
            cpa16(sW + buf * stageB + (r * GST + h8) * 2,
                  W + (size_t)(colBase + r) * K + k0 + h8);
        }
    };

    stage_cp(0, 0);
    cp_commit();
    cp_wait0();
    __syncthreads();

    for (int k0 = 0; k0 < K; k0 += 32) {
        const int cur = (k0 >> 5) & 1;
        const bool more = (k0 + 32 < K);
        if (more) { stage_cp(cur ^ 1, k0 + 32); cp_commit(); }
#pragma unroll
        for (int ks = 0; ks < 2; ks++) {
            uint32_t bF[2][4];
#pragma unroll
            for (int np = 0; np < 2; np++)
                ldsm4(bF[np], sW + cur * stageB + bOff + np * (16 * GST * 2) + ks * 32);
#pragma unroll
            for (int mt = 0; mt < 4; mt++) {
                uint32_t aF[4];
                ldsm4(aF, sA + cur * stageB + aOff + mt * (16 * GST * 2) + ks * 32);
#pragma unroll
                for (int nt = 0; nt < 4; nt++)
                    mma16(acc[mt][nt], aF, bF[nt >> 1][(nt & 1) * 2], bF[nt >> 1][(nt & 1) * 2 + 1]);
            }
        }
        if (more) { cp_wait0(); __syncthreads(); }
    }

    const int gid = lane >> 2, tig = lane & 3;
#pragma unroll
    for (int nt = 0; nt < 4; nt++) {
        const int col0 = colBase + wn * 32 + nt * 8 + tig * 2;
        const float bb0 = bias[col0], bb1 = bias[col0 + 1];
#pragma unroll
        for (int mt = 0; mt < 4; mt++) {
            const int row0 = rowBase + wm * 64 + mt * 16 + gid;
            const float v00 = acc[mt][nt][0] + bb0, v01 = acc[mt][nt][1] + bb1;
            const float v10 = acc[mt][nt][2] + bb0, v11 = acc[mt][nt][3] + bb1;
            if (mode == 0) {
                float* out = (float*)outv;
                *(float2*)&out[(size_t)row0 * E + col0]       = make_float2(v00, v01);
                *(float2*)&out[(size_t)(row0 + 8) * E + col0] = make_float2(v10, v11);
            } else if (mode == 1) {
                __half* out = (__half*)outv;
                const int b = row0 >> 11, s0 = row0 & (S - 1);
                const int h = col0 >> 6, d0 = col0 & 63;
                const size_t base = ((size_t)(b * H + h)) * S;
                *(uint32_t*)&out[(base + s0) * D + d0]     = f2h2(v00, v01);
                *(uint32_t*)&out[(base + s0 + 8) * D + d0] = f2h2(v10, v11);
            } else {
                __half* out = (__half*)outv;
                const int b = row0 >> 11, s0 = row0 & (S - 1);
                const int h = col0 >> 6, d0 = col0 & 63;
                const size_t base = ((size_t)(b * H + h)) * D;
                out[(base + d0) * S + s0]         = __float2half_rn(v00);
                out[(base + d0 + 1) * S + s0]     = __float2half_rn(v01);
                out[(base + d0) * S + s0 + 8]     = __float2half_rn(v10);
                out[(base + d0 + 1) * S + s0 + 8] = __float2half_rn(v11);
            }
        }
    }
}

// ============================================================
// Fused attention (fp16): register P->A fragments, no P smem.
// ============================================================
extern __shared__ char fsm[];

__global__ __launch_bounds__(256, 2) void fused_attn(
    const __half* __restrict__ q, const __half* __restrict__ k,
    const __half* __restrict__ vt, float* __restrict__ attn,
    __half* __restrict__ ctx)
{
    const int bh = blockIdx.x;
    const int it = 15 - blockIdx.y;
    const int nj = 2 * (it + 1);
    const int tid = threadIdx.x, lane = tid & 31, w = tid >> 5;
    const int gid = lane >> 2, tig = lane & 3;

    __half* QP = (__half*)fsm;              // 128*KST (Q staging)
    __half* Ks = QP + 128 * KST;            // 2 x 64*KST
    __half* Vs = Ks + 2 * 64 * KST;         // 2 x 64*KST

    const uint32_t sQP = (uint32_t)__cvta_generic_to_shared(QP);
    const uint32_t sK  = (uint32_t)__cvta_generic_to_shared(Ks);
    const uint32_t sV  = (uint32_t)__cvta_generic_to_shared(Vs);
    const uint32_t bufB = 64 * KST * 2;

    const __half* qbase = q + ((size_t)bh * S + (size_t)it * 128) * D;
    const __half* kbase = k + (size_t)bh * S * D;
    const __half* vbase = vt + (size_t)bh * D * S;

    const uint32_t aAddr = sQP + ((w * 16 + (lane & 7) + ((lane >> 3) & 1) * 8) * KST
                                  + (lane >> 4) * 8) * 2;
    const uint32_t bOff = (((lane & 7) + (lane >> 4) * 8) * KST
                           + ((lane >> 3) & 1) * 8) * 2;

    // ---- prologue: stage Q, prefetch K0 ----
#pragma unroll
    for (int t = 0; t < 4; t++) {
        const int c = tid + t * 256;
        const int r = c >> 3, c8 = (c & 7) * 8;
        cpa16(sQP + (r * KST + c8) * 2, qbase + r * 64 + c8);
    }
    cp_commit();
#pragma unroll
    for (int t = 0; t < 2; t++) {
        const int c = tid + t * 256;
        const int r = c >> 3, c8 = (c & 7) * 8;
        cpa16(sK + (r * KST + c8) * 2, kbase + (size_t)r * 64 + c8);
    }
    cp_commit();
    cp_wait0();
    __syncthreads();

    uint32_t aQ[4][4];
#pragma unroll
    for (int kc = 0; kc < 4; kc++) ldsm4(aQ[kc], aAddr + kc * 32);
    __syncthreads();

    float as[8][4];
    float Zacc[2] = {0.f, 0.f};

    // =================== PASS 1: Z (warp-local) ===================
    for (int jt = 0; jt < nj; jt++) {
        const uint32_t kb = sK + (jt & 1) * bufB + bOff;
        if (jt + 1 < nj) {
#pragma unroll
            for (int t = 0; t < 2; t++) {
                const int c = tid + t * 256;
                const int r = c >> 3, c8 = (c & 7) * 8;
                cpa16(sK + ((jt + 1) & 1) * bufB + (r * KST + c8) * 2,
                      kbase + (size_t)((jt + 1) * 64 + r) * 64 + c8);
            }
            cp_commit();
        }
#pragma unroll
        for (int nt = 0; nt < 8; nt++)
#pragma unroll
            for (int c = 0; c < 4; c++) as[nt][c] = 0.f;
#pragma unroll
        for (int kp = 0; kp < 4; kp++) {
#pragma unroll
            for (int np = 0; np < 4; np++) {
                uint32_t bF[4];
                ldsm4(bF, kb + np * (16 * KST * 2) + kp * 32);
                mma16(as[np * 2],     aQ[kp], bF[0], bF[1]);
                mma16(as[np * 2 + 1], aQ[kp], bF[2], bF[3]);
            }
        }
        const bool diag = (jt >= 2 * it);
#pragma unroll
        for (int h = 0; h < 2; h++) {
            const int li = it * 128 + w * 16 + gid + h * 8;
            float z = 0.f;
#pragma unroll
            for (int nt = 0; nt < 8; nt++) {
                const int lj = jt * 64 + nt * 8 + tig * 2;
                float e0 = __expf(as[nt][h * 2]     * 0.125f);
                float e1 = __expf(as[nt][h * 2 + 1] * 0.125f);
                if (diag) { if (lj > li) e0 = 0.f; if (lj + 1 > li) e1 = 0.f; }
                z += e0 + e1;
            }
            Zacc[h] += z;
        }
        if (jt + 1 < nj) { cp_wait0(); __syncthreads(); }
    }

    float Zi[2];
#pragma unroll
    for (int h = 0; h < 2; h++) {
        float z = Zacc[h];
        z += __shfl_xor_sync(0xffffffffu, z, 1);
        z += __shfl_xor_sync(0xffffffffu, z, 2);
        Zi[h] = 1.f / z;
    }

    // =================== PASS 2: p + P@V (register P) ===================
    __syncthreads();
#pragma unroll
    for (int t = 0; t < 2; t++) {
        const int c = tid + t * 256;
        const int r = c >> 3, c8 = (c & 7) * 8;
        cpa16(sK + (r * KST + c8) * 2, kbase + (size_t)r * 64 + c8);
        cpa16(sV + (r * KST + c8) * 2, vbase + (size_t)r * S + c8);
    }
    cp_commit();
    cp_wait0();
    __syncthreads();

    float cacc[8][4];
#pragma unroll
    for (int nt = 0; nt < 8; nt++)
#pragma unroll
        for (int c = 0; c < 4; c++) cacc[nt][c] = 0.f;

    const int gi0 = it * 128 + w * 16 + gid;

    for (int jt = 0; jt < nj; jt++) {
        const uint32_t kb = sK + (jt & 1) * bufB + bOff;
        const uint32_t vb = sV + (jt & 1) * bufB + bOff;
        if (jt + 1 < nj) {
#pragma unroll
            for (int t = 0; t < 2; t++) {
                const int c = tid + t * 256;
                const int r = c >> 3, c8 = (c & 7) * 8;
                cpa16(sK + ((jt + 1) & 1) * bufB + (r * KST + c8) * 2,
                      kbase + (size_t)((jt + 1) * 64 + r) * 64 + c8);
                cpa16(sV + ((jt + 1) & 1) * bufB + (r * KST + c8) * 2,
                      vbase + (size_t)r * S + (jt + 1) * 64 + c8);
            }
            cp_commit();
        }
#pragma unroll
        for (int nt = 0; nt < 8; nt++)
#pragma unroll
            for (int c = 0; c < 4; c++) as[nt][c] = 0.f;
#pragma unroll
        for (int kp = 0; kp < 4; kp++) {
#pragma unroll
            for (int np = 0; np < 4; np++) {
                uint32_t bF[4];
                ldsm4(bF, kb + np * (16 * KST * 2) + kp * 32);
                mma16(as[np * 2],     aQ[kp], bF[0], bF[1]);
                mma16(as[np * 2 + 1], aQ[kp], bF[2], bF[3]);
            }
        }
        // p = exp(s)/Z : write fp32 attn + pack fp16 A-fragments in regs
        const bool diag = (jt >= 2 * it);
        uint32_t pk[8][2];
        float* prow0 = attn + ((size_t)bh * S + gi0) * S + jt * 64;
        float* prow1 = prow0 + (size_t)8 * S;
#pragma unroll
        for (int nt = 0; nt < 8; nt++) {
            const int lj = jt * 64 + nt * 8 + tig * 2;
            float p0 = __expf(as[nt][0] * 0.125f) * Zi[0];
            float p1 = __expf(as[nt][1] * 0.125f) * Zi[0];
            float p2 = __expf(as[nt][2] * 0.125f) * Zi[1];
            float p3 = __expf(as[nt][3] * 0.125f) * Zi[1];
            if (diag) {
                if (lj > gi0)         p0 = 0.f;
                if (lj + 1 > gi0)     p1 = 0.f;
                if (lj > gi0 + 8)     p2 = 0.f;
                if (lj + 1 > gi0 + 8) p3 = 0.f;
            }
            *(float2*)(prow0 + nt * 8 + tig * 2) = make_float2(p0, p1);
            *(float2*)(prow1 + nt * 8 + tig * 2) = make_float2(p2, p3);
            pk[nt][0] = f2h2(p0, p1);
            pk[nt][1] = f2h2(p2, p3);
        }

        // ctx += P(16x64) @ V(64x64), P straight from registers
#pragma unroll
        for (int kp = 0; kp < 4; kp++) {
            const uint32_t aP[4] = { pk[2 * kp][0], pk[2 * kp][1],
                                     pk[2 * kp + 1][0], pk[2 * kp + 1][1] };
#pragma unroll
            for (int np = 0; np < 4; np++) {
                uint32_t bF[4];
                ldsm4(bF, vb + np * (16 * KST * 2) + kp * 32);
                mma16(cacc[np * 2],     aP, bF[0], bF[1]);
                mma16(cacc[np * 2 + 1], aP, bF[2], bF[3]);
            }
        }
        if (jt + 1 < nj) { cp_wait0(); __syncthreads(); }
    }

    // ctx epilogue: fp16 [b,s,h,d] == [M,E]
    const int b = bh >> 4, hh = bh & 15;
#pragma unroll
    for (int nt = 0; nt < 8; nt++) {
        const int d0 = nt * 8 + tig * 2;
        *(uint32_t*)&ctx[((size_t)(b * S + gi0)) * E + hh * D + d0] =
            f2h2(cacc[nt][0], cacc[nt][1]);
        *(uint32_t*)&ctx[((size_t)(b * S + gi0 + 8)) * E + hh * D + d0] =
            f2h2(cacc[nt][2], cacc[nt][3]);
    }

    // zero-fill columns beyond the causal edge
    const int zc0 = nj * 64;
    if (zc0 < S) {
        const int r = tid >> 1;
        float* row = attn + ((size_t)bh * S + it * 128 + r) * S;
        const float4 z = make_float4(0.f, 0.f, 0.f, 0.f);
        for (int c = zc0 + (tid & 1) * 4; c < S; c += 8)
            *(float4*)(row + c) = z;
    }
}

// ============================================================
// launch
// ============================================================
extern "C" void kernel_launch(void* const* d_in, const int* in_sizes, int n_in,
                              void* d_out_v, int out_size)
{
    const float* query = (const float*)d_in[0];
    const float* key_  = (const float*)d_in[1];
    const float* value = (const float*)d_in[2];
    const float* Wq = (const float*)d_in[4];
    const float* bq = (const float*)d_in[5];
    const float* Wk = (const float*)d_in[6];
    const float* bk = (const float*)d_in[7];
    const float* Wv = (const float*)d_in[8];
    const float* bv = (const float*)d_in[9];
    const float* Wo = (const float*)d_in[10];
    const float* bo = (const float*)d_in[11];
    float* d_out = (float*)d_out_v;

    __half *ahp, *whp, *qp, *kp, *vtp, *cp;
    float *op, *ap;
    cudaGetSymbolAddress((void**)&ahp, g_ah);
    cudaGetSymbolAddress((void**)&whp, g_wh);
    cudaGetSymbolAddress((void**)&qp,  g_q);
    cudaGetSymbolAddress((void**)&kp,  g_k);
    cudaGetSymbolAddress((void**)&vtp, g_vt);
    cudaGetSymbolAddress((void**)&cp,  g_ctx);
    cudaGetSymbolAddress((void**)&op,  g_out);
    cudaGetSymbolAddress((void**)&ap,  g_attn);

    float* out_ptr;
    float* attn_ptr;
    long long osz = (long long)out_size;
    if (osz >= (long long)OUT_N + (long long)ATT_N) {
        out_ptr = d_out; attn_ptr = d_out + OUT_N;
    } else if (osz == (long long)OUT_N) {
        out_ptr = d_out; attn_ptr = ap;
    } else {
        attn_ptr = d_out; out_ptr = op;
    }

    const int FUSED_SMEM = (128 * KST + 4 * 64 * KST) * 2;   // 55296 B
    cudaFuncSetAttribute(fused_attn, cudaFuncAttributeMaxDynamicSharedMemorySize,
                         FUSED_SMEM);

    const int NA = M_ROWS * E;   // 4,194,304
    const int NW = E * E;        // 1,048,576
    __half* ah0 = ahp;
    __half* ah1 = ahp + (size_t)NA;
    __half* ah2 = ahp + (size_t)2 * NA;
    __half* wq = whp;
    __half* wk = whp + (size_t)NW;
    __half* wv = whp + (size_t)2 * NW;
    __half* wo = whp + (size_t)3 * NW;

    // fp32 -> fp16 conversion of inputs + weights (7 tensors)
    CvtArgs ca;
    ca.src[0] = query; ca.src[1] = key_; ca.src[2] = value;
    ca.src[3] = Wq; ca.src[4] = Wk; ca.src[5] = Wv; ca.src[6] = Wo;
    ca.dst[0] = ah0; ca.dst[1] = ah1; ca.dst[2] = ah2;
    ca.dst[3] = wq; ca.dst[4] = wk; ca.dst[5] = wv; ca.dst[6] = wo;
    ca.n[0] = ca.n[1] = ca.n[2] = NA;
    ca.n[3] = ca.n[4] = ca.n[5] = ca.n[6] = NW;
    cvt_f2h<<<dim3(NA / 8 / 256, 1, 7), 256>>>(ca);

    // merged Q/K/V projections: one launch, z = 0/1/2 (pure fp16)
    gemm_h<<<dim3(E / 128, M_ROWS / 128, 3), 256>>>(
        ah0, ah1, ah2, wq, wk, wv, bq, bk, bv,
        qp, kp, vtp, 1, 1, 2, E);

    dim3 gF(Bn * H, 16);
    fused_attn<<<gF, 256, FUSED_SMEM>>>(qp, kp, vtp, attn_ptr, cp);

    // output projection (A = fp16 ctx)
    gemm_h<<<dim3(E / 128, M_ROWS / 128, 1), 256>>>(
        cp, cp, cp, wo, wo, wo, bo, bo, bo,
        out_ptr, out_ptr, out_ptr, 0, 0, 0, E);
}